// round 1
// baseline (speedup 1.0000x reference)
#include <cuda_runtime.h>
#include <math.h>

// ---------------- problem constants ----------------
#define BATCH  8
#define HGc    17
#define WGc    90
#define Lseq   1530            // HG*WG
#define Tseq   6120            // 4*L
#define BT     48960           // BATCH*Tseq
#define DMc    128
#define EXPC   256
#define NSC    128
#define NHC    4
#define HDC    64
#define PROJC  772
#define PHc    20
#define PWc    8
#define CINc   3
#define PATCHK 480             // CIN*PH*PW
#define NPATCH 12240           // BATCH*Lseq

// ---------------- device scratch (static, no allocs) ----------------
__device__ float g_patches[(size_t)NPATCH * PATCHK];
__device__ float g_emb    [(size_t)NPATCH * DMc];      // also reused as MLP hidden
__device__ float g_h      [(size_t)BT * DMc];
__device__ float g_hn     [(size_t)BT * DMc];
__device__ float g_proj   [(size_t)BT * PROJC];        // also reused as final r output
__device__ float g_xbc    [(size_t)BT * 512];
__device__ float g_dt     [(size_t)BT * NHC];
__device__ float g_dA     [(size_t)BT * NHC];
__device__ float g_dtx    [(size_t)BT * EXPC];
__device__ float g_y      [(size_t)BT * EXPC];
__device__ float g_z      [(size_t)BT * EXPC];
__device__ float g_xm     [(size_t)NPATCH * DMc];

// ---------------- generic tiled fp32 GEMM: C = act(A @ W^T + bias) (+resid) ----------------
// A: [M,K] row-major, W: [N,K] row-major (i.e. computes A @ W^T)
__global__ void gemm_abt(const float* __restrict__ A, const float* __restrict__ W,
                         const float* __restrict__ bias, const float* __restrict__ resid,
                         float* __restrict__ C, int M, int N, int K, int act)
{
    __shared__ float As[16][68];
    __shared__ float Ws[16][68];
    const int tid = threadIdx.x;          // 256 threads
    const int m0 = blockIdx.y * 64;
    const int n0 = blockIdx.x * 64;
    const int lk = tid & 15;              // k within chunk
    const int lr = tid >> 4;              // row within tile chunk
    const int tx = tid & 15;
    const int ty = tid >> 4;
    float acc[4][4] = {};
    for (int k0 = 0; k0 < K; k0 += 16) {
#pragma unroll
        for (int r = 0; r < 4; r++) {
            int mrow = m0 + lr + 16 * r;
            As[lk][lr + 16 * r] = (mrow < M) ? A[(size_t)mrow * K + k0 + lk] : 0.f;
            int nrow = n0 + lr + 16 * r;
            Ws[lk][lr + 16 * r] = (nrow < N) ? W[(size_t)nrow * K + k0 + lk] : 0.f;
        }
        __syncthreads();
#pragma unroll
        for (int kk = 0; kk < 16; kk++) {
            float a[4], b[4];
#pragma unroll
            for (int i = 0; i < 4; i++) a[i] = As[kk][ty * 4 + i];
#pragma unroll
            for (int j = 0; j < 4; j++) b[j] = Ws[kk][tx * 4 + j];
#pragma unroll
            for (int i = 0; i < 4; i++)
#pragma unroll
                for (int j = 0; j < 4; j++)
                    acc[i][j] = fmaf(a[i], b[j], acc[i][j]);
        }
        __syncthreads();
    }
#pragma unroll
    for (int i = 0; i < 4; i++) {
        int m = m0 + ty * 4 + i;
        if (m >= M) continue;
#pragma unroll
        for (int j = 0; j < 4; j++) {
            int n = n0 + tx * 4 + j;
            if (n >= N) continue;
            float v = acc[i][j];
            if (bias) v += bias[n];
            if (act == 1) v = 0.5f * v * (1.f + erff(v * 0.7071067811865475f));
            if (resid) v += resid[(size_t)m * N + n];
            C[(size_t)m * N + n] = v;
        }
    }
}

// ---------------- patch gather ----------------
__global__ void patch_gather(const float* __restrict__ x)
{
    int idx = blockIdx.x * blockDim.x + threadIdx.x;
    if (idx >= NPATCH * PATCHK) return;
    int q  = idx % PATCHK;
    int bl = idx / PATCHK;
    int c  = q / 160, rr = q % 160;
    int i  = rr / PWc, jj = rr % PWc;
    int b  = bl / Lseq, l = bl % Lseq;
    int hg = l / WGc,  wg = l % WGc;
    g_patches[idx] = x[(((size_t)(b * CINc + c) * 340) + hg * PHc + i) * 720 + wg * PWc + jj];
}

// ---------------- build concatenated 4-direction sequence ----------------
__global__ void build_h()
{
    int bl = blockIdx.x;
    int b = bl / Lseq, l = bl % Lseq;
    int hg = l / WGc, wg = l % WGc;
    int j = wg * HGc + hg;
    int tid = threadIdx.x;
    float v = g_emb[(size_t)bl * DMc + tid];
    size_t base = (size_t)b * Tseq;
    g_h[(base + l) * DMc + tid] = v;
    g_h[(base + Lseq + j) * DMc + tid] = v;
    g_h[(base + 2 * Lseq + (Lseq - 1 - l)) * DMc + tid] = v;
    g_h[(base + 3 * Lseq + (Lseq - 1 - j)) * DMc + tid] = v;
}

// ---------------- rmsnorm over 128 channels ----------------
__global__ void rmsnorm128(const float* __restrict__ X, const float* __restrict__ w,
                           float* __restrict__ Y)
{
    int row = blockIdx.x;
    int tid = threadIdx.x;   // 128
    float v = X[(size_t)row * DMc + tid];
    float s = v * v;
#pragma unroll
    for (int o = 16; o > 0; o >>= 1) s += __shfl_xor_sync(0xffffffffu, s, o);
    __shared__ float ws[4];
    if ((tid & 31) == 0) ws[tid >> 5] = s;
    __syncthreads();
    float tot = ws[0] + ws[1] + ws[2] + ws[3];
    float sc = rsqrtf(tot * (1.f / DMc) + 1e-5f);
    Y[(size_t)row * DMc + tid] = v * sc * w[tid];
}

// ---------------- causal depthwise conv (K=4) + silu over 512 xBC channels ----------------
__global__ void conv_silu(const float* __restrict__ cw, const float* __restrict__ cb)
{
    size_t idx = (size_t)blockIdx.x * blockDim.x + threadIdx.x;
    if (idx >= (size_t)BT * 512) return;
    int c  = (int)(idx & 511);
    int bt = (int)(idx >> 9);
    int t  = bt % Tseq;
    int b  = bt / Tseq;
    float acc = cb[c];
#pragma unroll
    for (int k = 0; k < 4; k++) {
        int tt = t + k - 3;
        if (tt >= 0)
            acc = fmaf(g_proj[((size_t)(b * Tseq + tt)) * PROJC + 256 + c], cw[c * 4 + k], acc);
    }
    float sg = 1.f / (1.f + expf(-acc));
    g_xbc[idx] = acc * sg;
}

// ---------------- dt = softplus(raw+bias); dA = exp(-exp(Alog)*dt) ----------------
__global__ void dt_kernel(const float* __restrict__ dtb, const float* __restrict__ alog)
{
    int idx = blockIdx.x * blockDim.x + threadIdx.x;
    if (idx >= BT * NHC) return;
    int h  = idx & 3;
    int bt = idx >> 2;
    float x = g_proj[(size_t)bt * PROJC + 768 + h] + dtb[h];
    float sp = (x > 20.f) ? x : log1pf(expf(x));
    float A  = -expf(alog[h]);
    g_dt[idx] = sp;
    g_dA[idx] = expf(sp * A);
}

// ---------------- dtx = dt * x_head ----------------
__global__ void dtx_kernel()
{
    size_t idx = (size_t)blockIdx.x * blockDim.x + threadIdx.x;
    if (idx >= (size_t)BT * EXPC) return;
    int c  = (int)(idx & 255);
    int bt = (int)(idx >> 8);
    g_dtx[idx] = g_dt[bt * 4 + (c >> 6)] * g_xbc[(size_t)bt * 512 + c];
}

// ---------------- sequential SSD scan: warp per (b,h,p), lane holds 4 states ----------------
__global__ void scan_kernel()
{
    int gw   = (blockIdx.x * blockDim.x + threadIdx.x) >> 5;  // 0..2047
    int lane = threadIdx.x & 31;
    int b = gw >> 8;                 // NH*HD = 256
    int r = gw & 255;
    int h = r >> 6;                  // HD = 64
    int p = r & 63;
    const float*  dAp = g_dA  + (size_t)b * Tseq * NHC + h;
    const float*  dxp = g_dtx + (size_t)b * Tseq * EXPC + h * HDC + p;
    const float4* B4  = (const float4*)(g_xbc + (size_t)b * Tseq * 512 + 256);
    const float4* C4  = (const float4*)(g_xbc + (size_t)b * Tseq * 512 + 384);
    float*        yp  = g_y   + (size_t)b * Tseq * EXPC + h * HDC + p;

    float sx = 0.f, sy = 0.f, sz = 0.f, sw = 0.f;
    float4 bv = B4[lane];
    float4 cv = C4[lane];
    float  da = dAp[0];
    float  xx = dxp[0];
    for (int t = 0; t < Tseq; t++) {
        float4 bn = bv, cn = cv;
        float d0 = da, x0 = xx;
        if (t + 1 < Tseq) {
            size_t o4 = (size_t)(t + 1) * 128 + lane;
            bv = B4[o4];
            cv = C4[o4];
            da = dAp[(size_t)(t + 1) * NHC];
            xx = dxp[(size_t)(t + 1) * EXPC];
        }
        sx = fmaf(sx, d0, x0 * bn.x);
        sy = fmaf(sy, d0, x0 * bn.y);
        sz = fmaf(sz, d0, x0 * bn.z);
        sw = fmaf(sw, d0, x0 * bn.w);
        float acc = sx * cn.x + sy * cn.y + sz * cn.z + sw * cn.w;
#pragma unroll
        for (int o = 16; o > 0; o >>= 1)
            acc += __shfl_xor_sync(0xffffffffu, acc, o);
        if (lane == 0) yp[(size_t)t * EXPC] = acc;
    }
}

// ---------------- (y + D*x) * silu(gate), rmsnorm(256) with gn_w ----------------
__global__ void gate_norm(const float* __restrict__ Dp, const float* __restrict__ gnw)
{
    int row = blockIdx.x;
    int tid = threadIdx.x;   // 256
    float xh = g_xbc[(size_t)row * 512 + tid];
    float yv = g_y[(size_t)row * EXPC + tid] + Dp[tid >> 6] * xh;
    float g  = g_proj[(size_t)row * PROJC + tid];
    float v  = yv * (g / (1.f + expf(-g)));
    float s = v * v;
#pragma unroll
    for (int o = 16; o > 0; o >>= 1) s += __shfl_xor_sync(0xffffffffu, s, o);
    __shared__ float ws[8];
    if ((tid & 31) == 0) ws[tid >> 5] = s;
    __syncthreads();
    float tot = 0.f;
#pragma unroll
    for (int i = 0; i < 8; i++) tot += ws[i];
    float sc = rsqrtf(tot * (1.f / EXPC) + 1e-5f);
    g_z[(size_t)row * EXPC + tid] = v * sc * gnw[tid];
}

// ---------------- combine the 4 directional outputs back to (B,L,DM) ----------------
__global__ void combine_kernel()
{
    int bl = blockIdx.x;
    int b = bl / Lseq, l = bl % Lseq;
    int hg = l / WGc, wg = l % WGc;
    int j = wg * HGc + hg;
    int tid = threadIdx.x;
    size_t base = (size_t)b * Tseq;
    float v = g_hn[(base + l) * DMc + tid]
            + g_hn[(base + Lseq + j) * DMc + tid]
            + g_hn[(base + 2 * Lseq + (Lseq - 1 - l)) * DMc + tid]
            + g_hn[(base + 3 * Lseq + (Lseq - 1 - j)) * DMc + tid];
    g_xm[(size_t)bl * DMc + tid] = v;
}

// ---------------- unpatchify to (B,CIN,340,720) ----------------
__global__ void unpatch(float* __restrict__ out)
{
    int idx = blockIdx.x * blockDim.x + threadIdx.x;
    if (idx >= NPATCH * PATCHK) return;
    int xc = idx % 720;
    int t1 = idx / 720;
    int y  = t1 % 340;
    int t2 = t1 / 340;
    int c  = t2 % 3;
    int b  = t2 / 3;
    int hg = y / PHc,  i  = y % PHc;
    int wg = xc / PWc, jj = xc % PWc;
    int l  = hg * WGc + wg;
    out[idx] = g_proj[((size_t)(b * Lseq + l)) * 480 + i * 24 + jj * 3 + c];
}

// ---------------- host orchestration ----------------
static float* sym_addr(const void* sym)
{
    void* p = nullptr;
    cudaGetSymbolAddress(&p, sym);
    return (float*)p;
}

extern "C" void kernel_launch(void* const* d_in, const int* in_sizes, int n_in,
                              void* d_out, int out_size)
{
    (void)in_sizes; (void)n_in; (void)out_size;
    const float* x       = (const float*)d_in[0];
    const float* W_pe    = (const float*)d_in[1];
    const float* b_pe    = (const float*)d_in[2];
    const float* norm_w  = (const float*)d_in[3];
    const float* in_w    = (const float*)d_in[4];
    const float* in_b    = (const float*)d_in[5];
    const float* conv_w  = (const float*)d_in[6];
    const float* conv_b  = (const float*)d_in[7];
    const float* dt_bias = (const float*)d_in[8];
    const float* A_log   = (const float*)d_in[9];
    const float* Dp      = (const float*)d_in[10];
    const float* gn_w    = (const float*)d_in[11];
    const float* out_w   = (const float*)d_in[12];
    const float* out_b   = (const float*)d_in[13];
    const float* normf_w = (const float*)d_in[14];
    const float* r1_w    = (const float*)d_in[15];
    const float* r1_b    = (const float*)d_in[16];
    const float* r2_w    = (const float*)d_in[17];
    const float* r2_b    = (const float*)d_in[18];
    float* out = (float*)d_out;

    float* patches = sym_addr(g_patches);
    float* emb     = sym_addr(g_emb);
    float* hbuf    = sym_addr(g_h);
    float* hn      = sym_addr(g_hn);
    float* proj    = sym_addr(g_proj);
    float* zbuf    = sym_addr(g_z);
    float* xm      = sym_addr(g_xm);

    // patch embed
    patch_gather<<<(NPATCH * PATCHK + 255) / 256, 256>>>(x);
    gemm_abt<<<dim3(2, (NPATCH + 63) / 64), 256>>>(patches, W_pe, b_pe, nullptr,
                                                   emb, NPATCH, DMc, PATCHK, 0);
    build_h<<<NPATCH, 128>>>();

    for (int l = 0; l < 4; l++) {
        rmsnorm128<<<BT, 128>>>(hbuf, norm_w + l * DMc, hn);
        gemm_abt<<<dim3((PROJC + 63) / 64, BT / 64), 256>>>(
            hn, in_w + (size_t)l * PROJC * DMc, in_b + l * PROJC, nullptr,
            proj, BT, PROJC, DMc, 0);
        conv_silu<<<(int)(((size_t)BT * 512 + 255) / 256), 256>>>(
            conv_w + l * 512 * 4, conv_b + l * 512);
        dt_kernel<<<(BT * NHC + 255) / 256, 256>>>(dt_bias + l * NHC, A_log + l * NHC);
        dtx_kernel<<<(int)(((size_t)BT * EXPC + 255) / 256), 256>>>();
        scan_kernel<<<512, 128>>>();
        gate_norm<<<BT, 256>>>(Dp + l * NHC, gn_w + l * EXPC);
        gemm_abt<<<dim3(2, BT / 64), 256>>>(
            zbuf, out_w + (size_t)l * DMc * EXPC, out_b + l * DMc, hbuf,
            hbuf, BT, DMc, EXPC, 0);
    }

    rmsnorm128<<<BT, 128>>>(hbuf, normf_w, hn);
    combine_kernel<<<NPATCH, 128>>>();
    // MLP: xm -> gelu(xm@r1^T + b1) -> @r2^T + b2
    gemm_abt<<<dim3(2, (NPATCH + 63) / 64), 256>>>(xm, r1_w, r1_b, nullptr,
                                                   emb, NPATCH, DMc, DMc, 1);
    gemm_abt<<<dim3(8, (NPATCH + 63) / 64), 256>>>(emb, r2_w, r2_b, nullptr,
                                                   proj, NPATCH, 480, DMc, 0);
    unpatch<<<(NPATCH * PATCHK + 255) / 256, 256>>>(out);
}

// round 2
// speedup vs baseline: 1.0656x; 1.0656x over previous
#include <cuda_runtime.h>
#include <math.h>

// ---------------- problem constants ----------------
#define BATCH  8
#define HGc    17
#define WGc    90
#define Lseq   1530            // HG*WG
#define Tseq   6120            // 4*L
#define BT     48960           // BATCH*Tseq
#define DMc    128
#define EXPC   256
#define NSC    128
#define NHC    4
#define HDC    64
#define PHc    20
#define PWc    8
#define CINc   3
#define PATCHK 480             // CIN*PH*PW
#define NPATCH 12240           // BATCH*Lseq
#define PROJW  768             // gate(256)+xBC(512); dt handled separately

// ---------------- device scratch (static, no allocs) ----------------
__device__ float g_patches[(size_t)NPATCH * PATCHK];
__device__ float g_emb    [(size_t)NPATCH * DMc];      // also reused as MLP hidden
__device__ float g_h      [(size_t)BT * DMc];
__device__ float g_hn     [(size_t)BT * DMc];
__device__ float g_proj   [(size_t)BT * PROJW];        // also reused as final r output
__device__ float g_xbc    [(size_t)BT * 512];
__device__ float g_dt     [(size_t)BT * NHC];
__device__ float g_dA     [(size_t)BT * NHC];
__device__ float g_dtx    [(size_t)BT * EXPC];
__device__ float g_y      [(size_t)BT * EXPC];
__device__ float g_z      [(size_t)BT * EXPC];
__device__ float g_xm     [(size_t)NPATCH * DMc];

// ---------------- 128x128x16 double-buffered fp32 GEMM ----------------
// C[M,N](ld=ldc) = act(A[M,K] @ W[N,K]^T + bias) (+resid)
#define BM 128
#define BN 128
#define BK 16

__global__ __launch_bounds__(256, 2)
void gemm128(const float* __restrict__ A, const float* __restrict__ W,
             const float* __restrict__ bias, const float* __restrict__ resid,
             float* __restrict__ C, int M, int N, int K, int ldc, int act)
{
    __shared__ __align__(16) float As[2][BK][BM + 4];
    __shared__ __align__(16) float Bs[2][BK][BN + 4];
    const int tid = threadIdx.x;          // 256 threads
    const int m0 = blockIdx.y * BM;
    const int n0 = blockIdx.x * BN;
    const int lr = tid >> 2;              // 0..63
    const int lc = (tid & 3) << 2;        // 0,4,8,12
    const int tx = tid & 15;
    const int ty = tid >> 4;

    const int mA0 = m0 + lr, mA1 = m0 + lr + 64;
    const int nB0 = n0 + lr, nB1 = n0 + lr + 64;
    const bool okA0 = mA0 < M, okA1 = mA1 < M;
    const bool okB0 = nB0 < N, okB1 = nB1 < N;
    const float4 z4 = make_float4(0.f, 0.f, 0.f, 0.f);

    float acc[8][8];
#pragma unroll
    for (int i = 0; i < 8; i++)
#pragma unroll
        for (int j = 0; j < 8; j++) acc[i][j] = 0.f;

    // prefetch chunk 0
    float4 ra0 = okA0 ? *(const float4*)(A + (size_t)mA0 * K + lc) : z4;
    float4 ra1 = okA1 ? *(const float4*)(A + (size_t)mA1 * K + lc) : z4;
    float4 rb0 = okB0 ? *(const float4*)(W + (size_t)nB0 * K + lc) : z4;
    float4 rb1 = okB1 ? *(const float4*)(W + (size_t)nB1 * K + lc) : z4;
    As[0][lc + 0][lr] = ra0.x; As[0][lc + 1][lr] = ra0.y;
    As[0][lc + 2][lr] = ra0.z; As[0][lc + 3][lr] = ra0.w;
    As[0][lc + 0][lr + 64] = ra1.x; As[0][lc + 1][lr + 64] = ra1.y;
    As[0][lc + 2][lr + 64] = ra1.z; As[0][lc + 3][lr + 64] = ra1.w;
    Bs[0][lc + 0][lr] = rb0.x; Bs[0][lc + 1][lr] = rb0.y;
    Bs[0][lc + 2][lr] = rb0.z; Bs[0][lc + 3][lr] = rb0.w;
    Bs[0][lc + 0][lr + 64] = rb1.x; Bs[0][lc + 1][lr + 64] = rb1.y;
    Bs[0][lc + 2][lr + 64] = rb1.z; Bs[0][lc + 3][lr + 64] = rb1.w;

    const int nch = K / BK;
    int buf = 0;
    for (int ch = 0; ch < nch; ch++) {
        __syncthreads();
        if (ch + 1 < nch) {
            int kof = (ch + 1) * BK + lc;
            ra0 = okA0 ? *(const float4*)(A + (size_t)mA0 * K + kof) : z4;
            ra1 = okA1 ? *(const float4*)(A + (size_t)mA1 * K + kof) : z4;
            rb0 = okB0 ? *(const float4*)(W + (size_t)nB0 * K + kof) : z4;
            rb1 = okB1 ? *(const float4*)(W + (size_t)nB1 * K + kof) : z4;
        }
#pragma unroll
        for (int kk = 0; kk < BK; kk++) {
            float4 a0 = *(const float4*)&As[buf][kk][ty * 8];
            float4 a1 = *(const float4*)&As[buf][kk][ty * 8 + 4];
            float4 b0 = *(const float4*)&Bs[buf][kk][tx * 8];
            float4 b1 = *(const float4*)&Bs[buf][kk][tx * 8 + 4];
            float av[8] = {a0.x, a0.y, a0.z, a0.w, a1.x, a1.y, a1.z, a1.w};
            float bv[8] = {b0.x, b0.y, b0.z, b0.w, b1.x, b1.y, b1.z, b1.w};
#pragma unroll
            for (int i = 0; i < 8; i++)
#pragma unroll
                for (int j = 0; j < 8; j++)
                    acc[i][j] = fmaf(av[i], bv[j], acc[i][j]);
        }
        if (ch + 1 < nch) {
            int nb = buf ^ 1;
            As[nb][lc + 0][lr] = ra0.x; As[nb][lc + 1][lr] = ra0.y;
            As[nb][lc + 2][lr] = ra0.z; As[nb][lc + 3][lr] = ra0.w;
            As[nb][lc + 0][lr + 64] = ra1.x; As[nb][lc + 1][lr + 64] = ra1.y;
            As[nb][lc + 2][lr + 64] = ra1.z; As[nb][lc + 3][lr + 64] = ra1.w;
            Bs[nb][lc + 0][lr] = rb0.x; Bs[nb][lc + 1][lr] = rb0.y;
            Bs[nb][lc + 2][lr] = rb0.z; Bs[nb][lc + 3][lr] = rb0.w;
            Bs[nb][lc + 0][lr + 64] = rb1.x; Bs[nb][lc + 1][lr + 64] = rb1.y;
            Bs[nb][lc + 2][lr + 64] = rb1.z; Bs[nb][lc + 3][lr + 64] = rb1.w;
        }
        buf ^= 1;
    }

#pragma unroll
    for (int i = 0; i < 8; i++) {
        int m = m0 + ty * 8 + i;
        if (m >= M) continue;
        float* Crow = C + (size_t)m * ldc;
        const float* Rrow = resid ? resid + (size_t)m * ldc : (const float*)0;
#pragma unroll
        for (int j4 = 0; j4 < 8; j4 += 4) {
            int n = n0 + tx * 8 + j4;
            if (n >= N) continue;
            float4 v = make_float4(acc[i][j4], acc[i][j4 + 1], acc[i][j4 + 2], acc[i][j4 + 3]);
            if (bias) {
                float4 b4 = *(const float4*)(bias + n);
                v.x += b4.x; v.y += b4.y; v.z += b4.z; v.w += b4.w;
            }
            if (act == 1) {
                v.x = 0.5f * v.x * (1.f + erff(v.x * 0.7071067811865475f));
                v.y = 0.5f * v.y * (1.f + erff(v.y * 0.7071067811865475f));
                v.z = 0.5f * v.z * (1.f + erff(v.z * 0.7071067811865475f));
                v.w = 0.5f * v.w * (1.f + erff(v.w * 0.7071067811865475f));
            }
            if (Rrow) {
                float4 r4 = *(const float4*)(Rrow + n);
                v.x += r4.x; v.y += r4.y; v.z += r4.z; v.w += r4.w;
            }
            *(float4*)(Crow + n) = v;
        }
    }
}

// ---------------- patch gather ----------------
__global__ void patch_gather(const float* __restrict__ x)
{
    int idx = blockIdx.x * blockDim.x + threadIdx.x;
    if (idx >= NPATCH * PATCHK) return;
    int q  = idx % PATCHK;
    int bl = idx / PATCHK;
    int c  = q / 160, rr = q % 160;
    int i  = rr / PWc, jj = rr % PWc;
    int b  = bl / Lseq, l = bl % Lseq;
    int hg = l / WGc,  wg = l % WGc;
    g_patches[idx] = x[(((size_t)(b * CINc + c) * 340) + hg * PHc + i) * 720 + wg * PWc + jj];
}

// ---------------- build concatenated 4-direction sequence ----------------
__global__ void build_h()
{
    int bl = blockIdx.x;
    int b = bl / Lseq, l = bl % Lseq;
    int hg = l / WGc, wg = l % WGc;
    int j = wg * HGc + hg;
    int tid = threadIdx.x;
    float v = g_emb[(size_t)bl * DMc + tid];
    size_t base = (size_t)b * Tseq;
    g_h[(base + l) * DMc + tid] = v;
    g_h[(base + Lseq + j) * DMc + tid] = v;
    g_h[(base + 2 * Lseq + (Lseq - 1 - l)) * DMc + tid] = v;
    g_h[(base + 3 * Lseq + (Lseq - 1 - j)) * DMc + tid] = v;
}

// ---------------- rmsnorm over 128 channels ----------------
__global__ void rmsnorm128(const float* __restrict__ X, const float* __restrict__ w,
                           float* __restrict__ Y)
{
    int row = blockIdx.x;
    int tid = threadIdx.x;   // 128
    float v = X[(size_t)row * DMc + tid];
    float s = v * v;
#pragma unroll
    for (int o = 16; o > 0; o >>= 1) s += __shfl_xor_sync(0xffffffffu, s, o);
    __shared__ float ws[4];
    if ((tid & 31) == 0) ws[tid >> 5] = s;
    __syncthreads();
    float tot = ws[0] + ws[1] + ws[2] + ws[3];
    float sc = rsqrtf(tot * (1.f / DMc) + 1e-5f);
    Y[(size_t)row * DMc + tid] = v * sc * w[tid];
}

// ---------------- fused dt head: dt = softplus(hn.w_dt + b + dtb); dA ----------------
__global__ void dt_fused(const float* __restrict__ hn, const float* __restrict__ w,
                         const float* __restrict__ inb, const float* __restrict__ dtb,
                         const float* __restrict__ alog)
{
    int warp = (blockIdx.x * blockDim.x + threadIdx.x) >> 5;
    if (warp >= BT) return;
    int lane = threadIdx.x & 31;
    float4 hv = ((const float4*)(hn + (size_t)warp * DMc))[lane];
#pragma unroll
    for (int h = 0; h < 4; h++) {
        float4 wv = ((const float4*)(w + (size_t)(768 + h) * DMc))[lane];
        float d = hv.x * wv.x + hv.y * wv.y + hv.z * wv.z + hv.w * wv.w;
#pragma unroll
        for (int o = 16; o > 0; o >>= 1) d += __shfl_xor_sync(0xffffffffu, d, o);
        if (lane == 0) {
            float xv = d + inb[768 + h] + dtb[h];
            float sp = (xv > 20.f) ? xv : log1pf(expf(xv));
            g_dt[warp * 4 + h] = sp;
            g_dA[warp * 4 + h] = expf(-expf(alog[h]) * sp);
        }
    }
}

// ---------------- causal depthwise conv (K=4) + silu over 512 xBC channels ----------------
__global__ void conv_silu(const float* __restrict__ cw, const float* __restrict__ cb)
{
    size_t idx = (size_t)blockIdx.x * blockDim.x + threadIdx.x;
    if (idx >= (size_t)BT * 512) return;
    int c  = (int)(idx & 511);
    int bt = (int)(idx >> 9);
    int t  = bt % Tseq;
    int b  = bt / Tseq;
    float acc = cb[c];
#pragma unroll
    for (int k = 0; k < 4; k++) {
        int tt = t + k - 3;
        if (tt >= 0)
            acc = fmaf(g_proj[((size_t)(b * Tseq + tt)) * PROJW + 256 + c], cw[c * 4 + k], acc);
    }
    float sg = 1.f / (1.f + expf(-acc));
    g_xbc[idx] = acc * sg;
}

// ---------------- dtx = dt * x_head ----------------
__global__ void dtx_kernel()
{
    size_t idx = (size_t)blockIdx.x * blockDim.x + threadIdx.x;
    if (idx >= (size_t)BT * EXPC) return;
    int c  = (int)(idx & 255);
    int bt = (int)(idx >> 8);
    g_dtx[idx] = g_dt[bt * 4 + (c >> 6)] * g_xbc[(size_t)bt * 512 + c];
}

// ---------------- SSD scan: warp per (b,h,2p), fused dual reduce ----------------
__global__ __launch_bounds__(128)
void scan_kernel()
{
    int bb   = blockIdx.x;            // 0..255
    int b    = bb >> 5;
    int h    = (bb >> 3) & 3;
    int pb   = bb & 7;
    int widx = threadIdx.x >> 5;
    int lane = threadIdx.x & 31;
    int p    = pb * 8 + widx * 2;

    const float*  dAp = g_dA + (size_t)b * Tseq * NHC + h;
    const float2* dxp = (const float2*)(g_dtx + (size_t)b * Tseq * EXPC + h * HDC + p);
    const float4* B4  = (const float4*)(g_xbc + (size_t)b * Tseq * 512 + 256);
    const float4* C4  = (const float4*)(g_xbc + (size_t)b * Tseq * 512 + 384);
    float* yp = g_y + (size_t)b * Tseq * EXPC + h * HDC + p + (lane >> 4);
    bool doStore = ((lane & 15) == 0);

    float4 s0 = make_float4(0.f, 0.f, 0.f, 0.f);
    float4 s1 = make_float4(0.f, 0.f, 0.f, 0.f);
    float4 bv = B4[lane], cv = C4[lane];
    float  da = dAp[0];
    float2 xx = dxp[0];
    for (int t = 0; t < Tseq; t++) {
        float4 bn = bv, cn = cv;
        float d0 = da; float2 x0 = xx;
        if (t + 1 < Tseq) {
            size_t o4 = (size_t)(t + 1) * 128 + lane;
            bv = B4[o4]; cv = C4[o4];
            da = dAp[(size_t)(t + 1) * NHC];
            xx = dxp[(size_t)(t + 1) * (EXPC / 2)];
        }
        s0.x = fmaf(s0.x, d0, x0.x * bn.x);
        s0.y = fmaf(s0.y, d0, x0.x * bn.y);
        s0.z = fmaf(s0.z, d0, x0.x * bn.z);
        s0.w = fmaf(s0.w, d0, x0.x * bn.w);
        s1.x = fmaf(s1.x, d0, x0.y * bn.x);
        s1.y = fmaf(s1.y, d0, x0.y * bn.y);
        s1.z = fmaf(s1.z, d0, x0.y * bn.z);
        s1.w = fmaf(s1.w, d0, x0.y * bn.w);
        float a0 = s0.x * cn.x + s0.y * cn.y + s0.z * cn.z + s0.w * cn.w;
        float a1 = s1.x * cn.x + s1.y * cn.y + s1.z * cn.z + s1.w * cn.w;
        float u = a0 + __shfl_xor_sync(0xffffffffu, a0, 16);
        float v = a1 + __shfl_xor_sync(0xffffffffu, a1, 16);
        float w = (lane & 16) ? v : u;
        w += __shfl_xor_sync(0xffffffffu, w, 8);
        w += __shfl_xor_sync(0xffffffffu, w, 4);
        w += __shfl_xor_sync(0xffffffffu, w, 2);
        w += __shfl_xor_sync(0xffffffffu, w, 1);
        if (doStore) yp[(size_t)t * EXPC] = w;
    }
}

// ---------------- (y + D*x) * silu(gate), rmsnorm(256) with gn_w ----------------
__global__ void gate_norm(const float* __restrict__ Dp, const float* __restrict__ gnw)
{
    int row = blockIdx.x;
    int tid = threadIdx.x;   // 256
    float xh = g_xbc[(size_t)row * 512 + tid];
    float yv = g_y[(size_t)row * EXPC + tid] + Dp[tid >> 6] * xh;
    float g  = g_proj[(size_t)row * PROJW + tid];
    float v  = yv * (g / (1.f + expf(-g)));
    float s = v * v;
#pragma unroll
    for (int o = 16; o > 0; o >>= 1) s += __shfl_xor_sync(0xffffffffu, s, o);
    __shared__ float ws[8];
    if ((tid & 31) == 0) ws[tid >> 5] = s;
    __syncthreads();
    float tot = 0.f;
#pragma unroll
    for (int i = 0; i < 8; i++) tot += ws[i];
    float sc = rsqrtf(tot * (1.f / EXPC) + 1e-5f);
    g_z[(size_t)row * EXPC + tid] = v * sc * gnw[tid];
}

// ---------------- combine the 4 directional outputs back to (B,L,DM) ----------------
__global__ void combine_kernel()
{
    int bl = blockIdx.x;
    int b = bl / Lseq, l = bl % Lseq;
    int hg = l / WGc, wg = l % WGc;
    int j = wg * HGc + hg;
    int tid = threadIdx.x;
    size_t base = (size_t)b * Tseq;
    float v = g_hn[(base + l) * DMc + tid]
            + g_hn[(base + Lseq + j) * DMc + tid]
            + g_hn[(base + 2 * Lseq + (Lseq - 1 - l)) * DMc + tid]
            + g_hn[(base + 3 * Lseq + (Lseq - 1 - j)) * DMc + tid];
    g_xm[(size_t)bl * DMc + tid] = v;
}

// ---------------- unpatchify to (B,CIN,340,720) ----------------
__global__ void unpatch(float* __restrict__ out)
{
    int idx = blockIdx.x * blockDim.x + threadIdx.x;
    if (idx >= NPATCH * PATCHK) return;
    int xc = idx % 720;
    int t1 = idx / 720;
    int y  = t1 % 340;
    int t2 = t1 / 340;
    int c  = t2 % 3;
    int b  = t2 / 3;
    int hg = y / PHc,  i  = y % PHc;
    int wg = xc / PWc, jj = xc % PWc;
    int l  = hg * WGc + wg;
    out[idx] = g_proj[((size_t)(b * Lseq + l)) * 480 + i * 24 + jj * 3 + c];
}

// ---------------- host orchestration ----------------
static float* sym_addr(const void* sym)
{
    void* p = nullptr;
    cudaGetSymbolAddress(&p, sym);
    return (float*)p;
}

extern "C" void kernel_launch(void* const* d_in, const int* in_sizes, int n_in,
                              void* d_out, int out_size)
{
    (void)in_sizes; (void)n_in; (void)out_size;
    const float* x       = (const float*)d_in[0];
    const float* W_pe    = (const float*)d_in[1];
    const float* b_pe    = (const float*)d_in[2];
    const float* norm_w  = (const float*)d_in[3];
    const float* in_w    = (const float*)d_in[4];
    const float* in_b    = (const float*)d_in[5];
    const float* conv_w  = (const float*)d_in[6];
    const float* conv_b  = (const float*)d_in[7];
    const float* dt_bias = (const float*)d_in[8];
    const float* A_log   = (const float*)d_in[9];
    const float* Dp      = (const float*)d_in[10];
    const float* gn_w    = (const float*)d_in[11];
    const float* out_w   = (const float*)d_in[12];
    const float* out_b   = (const float*)d_in[13];
    const float* normf_w = (const float*)d_in[14];
    const float* r1_w    = (const float*)d_in[15];
    const float* r1_b    = (const float*)d_in[16];
    const float* r2_w    = (const float*)d_in[17];
    const float* r2_b    = (const float*)d_in[18];
    float* out = (float*)d_out;

    float* patches = sym_addr(g_patches);
    float* emb     = sym_addr(g_emb);
    float* hbuf    = sym_addr(g_h);
    float* hn      = sym_addr(g_hn);
    float* proj    = sym_addr(g_proj);
    float* zbuf    = sym_addr(g_z);
    float* xm      = sym_addr(g_xm);

    // patch embed: emb = patches @ W_pe^T + b_pe
    patch_gather<<<(NPATCH * PATCHK + 255) / 256, 256>>>(x);
    gemm128<<<dim3(1, (NPATCH + BM - 1) / BM), 256>>>(patches, W_pe, b_pe, nullptr,
                                                      emb, NPATCH, DMc, PATCHK, DMc, 0);
    build_h<<<NPATCH, 128>>>();

    for (int l = 0; l < 4; l++) {
        const float* iw = in_w + (size_t)l * 772 * DMc;
        const float* ib = in_b + (size_t)l * 772;
        rmsnorm128<<<BT, 128>>>(hbuf, norm_w + l * DMc, hn);
        // in_proj (first 768 cols only)
        gemm128<<<dim3(PROJW / BN, (BT + BM - 1) / BM), 256>>>(
            hn, iw, ib, nullptr, proj, BT, PROJW, DMc, PROJW, 0);
        dt_fused<<<BT / 8, 256>>>(hn, iw, ib, dt_bias + l * NHC, A_log + l * NHC);
        conv_silu<<<(int)(((size_t)BT * 512 + 255) / 256), 256>>>(
            conv_w + l * 512 * 4, conv_b + l * 512);
        dtx_kernel<<<(int)(((size_t)BT * EXPC + 255) / 256), 256>>>();
        scan_kernel<<<256, 128>>>();
        gate_norm<<<BT, 256>>>(Dp + l * NHC, gn_w + l * EXPC);
        gemm128<<<dim3(1, (BT + BM - 1) / BM), 256>>>(
            zbuf, out_w + (size_t)l * DMc * EXPC, out_b + l * DMc, hbuf,
            hbuf, BT, DMc, EXPC, DMc, 0);
    }

    rmsnorm128<<<BT, 128>>>(hbuf, normf_w, hn);
    combine_kernel<<<NPATCH, 128>>>();
    // MLP: xm -> gelu(xm@r1^T + b1) -> @r2^T + b2
    gemm128<<<dim3(1, (NPATCH + BM - 1) / BM), 256>>>(xm, r1_w, r1_b, nullptr,
                                                      emb, NPATCH, DMc, DMc, DMc, 1);
    gemm128<<<dim3((480 + BN - 1) / BN, (NPATCH + BM - 1) / BM), 256>>>(
        emb, r2_w, r2_b, nullptr, proj, NPATCH, 480, DMc, 480, 0);
    unpatch<<<(NPATCH * PATCHK + 255) / 256, 256>>>(out);
}

// round 3
// speedup vs baseline: 2.5078x; 2.3535x over previous
#include <cuda_runtime.h>
#include <math.h>

// ---------------- problem constants ----------------
#define BATCH  8
#define HGc    17
#define WGc    90
#define Lseq   1530            // HG*WG
#define Tseq   6120            // 4*L
#define BT     48960           // BATCH*Tseq
#define DMc    128
#define EXPC   256
#define NHC    4
#define HDC    64
#define PHc    20
#define PWc    8
#define CINc   3
#define PATCHK 480             // CIN*PH*PW
#define NPATCH 12240           // BATCH*Lseq
#define PROJW  768             // gate(256)+xBC(512); dt handled separately
#define SEGS   8
#define QSEG   765             // Tseq / SEGS

// ---------------- device scratch (static, no allocs) ----------------
__device__ float g_patches[(size_t)NPATCH * PATCHK];
__device__ float g_emb    [(size_t)NPATCH * DMc];      // reused as MLP hidden
__device__ float g_h      [(size_t)BT * DMc];
__device__ float g_hn     [(size_t)BT * DMc];
__device__ float g_proj   [(size_t)BT * PROJW];        // reused as final r output
__device__ float g_xbc    [(size_t)BT * 512];
__device__ float g_dt     [(size_t)BT * NHC];
__device__ float g_dA     [(size_t)BT * NHC];
__device__ float g_dtx    [(size_t)BT * EXPC];
__device__ float g_y      [(size_t)BT * EXPC];
__device__ float g_z      [(size_t)BT * EXPC];
__device__ float g_xm     [(size_t)NPATCH * DMc];
__device__ float g_e      [(size_t)32 * Tseq];                 // cumprod dA per (b,h)
__device__ float g_spart  [(size_t)32 * SEGS * 64 * 128];      // segment-final partial states
__device__ float g_sinit  [(size_t)32 * SEGS * 64 * 128];      // segment initial states

// ---------------- f32x2 helpers ----------------
union F4U { float4 f; unsigned long long u[2]; };

__device__ __forceinline__ unsigned long long ffma2(unsigned long long a,
                                                    unsigned long long b,
                                                    unsigned long long c)
{
    unsigned long long d;
    asm("fma.rn.f32x2 %0, %1, %2, %3;" : "=l"(d) : "l"(a), "l"(b), "l"(c));
    return d;
}

// ---------------- 128x128x16 double-buffered f32x2 GEMM ----------------
// C[M,N](ld=ldc) = epilogue(A[M,K] @ W[N,K]^T + bias)
// mode 0: (+resid) plain;  mode 1: gelu;  mode 2: scatter into 4 directional rows of g_h
#define BM 128
#define BN 128
#define BK 16

__global__ __launch_bounds__(256, 2)
void gemm128(const float* __restrict__ A, const float* __restrict__ W,
             const float* __restrict__ bias, const float* __restrict__ resid,
             float* __restrict__ C, int M, int N, int K, int ldc, int mode)
{
    __shared__ __align__(16) float As[2][BK][2 * BM];   // duplicated A
    __shared__ __align__(16) float Bs[2][BK][BN];
    const int tid = threadIdx.x;          // 256 threads
    const int m0 = blockIdx.y * BM;
    const int n0 = blockIdx.x * BN;
    const int lr = tid >> 2;              // 0..63
    const int lc = (tid & 3) << 2;        // 0,4,8,12
    const int tx = tid & 15;
    const int ty = tid >> 4;

    const int mA0 = m0 + lr, mA1 = m0 + lr + 64;
    const int nB0 = n0 + lr, nB1 = n0 + lr + 64;
    const bool okA0 = mA0 < M, okA1 = mA1 < M;
    const bool okB0 = nB0 < N, okB1 = nB1 < N;
    const float4 z4 = make_float4(0.f, 0.f, 0.f, 0.f);

    unsigned long long acc2[8][4];
#pragma unroll
    for (int i = 0; i < 8; i++)
#pragma unroll
        for (int j = 0; j < 4; j++) acc2[i][j] = 0ull;

    float4 ra0 = okA0 ? *(const float4*)(A + (size_t)mA0 * K + lc) : z4;
    float4 ra1 = okA1 ? *(const float4*)(A + (size_t)mA1 * K + lc) : z4;
    float4 rb0 = okB0 ? *(const float4*)(W + (size_t)nB0 * K + lc) : z4;
    float4 rb1 = okB1 ? *(const float4*)(W + (size_t)nB1 * K + lc) : z4;
    {
        float a0[4] = {ra0.x, ra0.y, ra0.z, ra0.w};
        float a1[4] = {ra1.x, ra1.y, ra1.z, ra1.w};
        float b0[4] = {rb0.x, rb0.y, rb0.z, rb0.w};
        float b1[4] = {rb1.x, rb1.y, rb1.z, rb1.w};
#pragma unroll
        for (int q = 0; q < 4; q++) {
            As[0][lc + q][2 * lr] = a0[q];  As[0][lc + q][2 * lr + 1] = a0[q];
            As[0][lc + q][2 * (lr + 64)] = a1[q];  As[0][lc + q][2 * (lr + 64) + 1] = a1[q];
            Bs[0][lc + q][lr] = b0[q];
            Bs[0][lc + q][lr + 64] = b1[q];
        }
    }

    const int nch = K / BK;
    int buf = 0;
    for (int ch = 0; ch < nch; ch++) {
        __syncthreads();
        if (ch + 1 < nch) {
            int kof = (ch + 1) * BK + lc;
            ra0 = okA0 ? *(const float4*)(A + (size_t)mA0 * K + kof) : z4;
            ra1 = okA1 ? *(const float4*)(A + (size_t)mA1 * K + kof) : z4;
            rb0 = okB0 ? *(const float4*)(W + (size_t)nB0 * K + kof) : z4;
            rb1 = okB1 ? *(const float4*)(W + (size_t)nB1 * K + kof) : z4;
        }
#pragma unroll
        for (int kk = 0; kk < BK; kk++) {
            F4U ad0, ad1, ad2, ad3, bb0, bb1;
            ad0.f = *(const float4*)&As[buf][kk][(ty * 8 + 0) * 2];
            ad1.f = *(const float4*)&As[buf][kk][(ty * 8 + 2) * 2];
            ad2.f = *(const float4*)&As[buf][kk][(ty * 8 + 4) * 2];
            ad3.f = *(const float4*)&As[buf][kk][(ty * 8 + 6) * 2];
            bb0.f = *(const float4*)&Bs[buf][kk][tx * 8];
            bb1.f = *(const float4*)&Bs[buf][kk][tx * 8 + 4];
            unsigned long long ap[8] = {ad0.u[0], ad0.u[1], ad1.u[0], ad1.u[1],
                                        ad2.u[0], ad2.u[1], ad3.u[0], ad3.u[1]};
            unsigned long long bp[4] = {bb0.u[0], bb0.u[1], bb1.u[0], bb1.u[1]};
#pragma unroll
            for (int i = 0; i < 8; i++)
#pragma unroll
                for (int j = 0; j < 4; j++)
                    acc2[i][j] = ffma2(ap[i], bp[j], acc2[i][j]);
        }
        if (ch + 1 < nch) {
            int nb = buf ^ 1;
            float a0[4] = {ra0.x, ra0.y, ra0.z, ra0.w};
            float a1[4] = {ra1.x, ra1.y, ra1.z, ra1.w};
            float b0[4] = {rb0.x, rb0.y, rb0.z, rb0.w};
            float b1[4] = {rb1.x, rb1.y, rb1.z, rb1.w};
#pragma unroll
            for (int q = 0; q < 4; q++) {
                As[nb][lc + q][2 * lr] = a0[q];  As[nb][lc + q][2 * lr + 1] = a0[q];
                As[nb][lc + q][2 * (lr + 64)] = a1[q];  As[nb][lc + q][2 * (lr + 64) + 1] = a1[q];
                Bs[nb][lc + q][lr] = b0[q];
                Bs[nb][lc + q][lr + 64] = b1[q];
            }
        }
        buf ^= 1;
    }

#pragma unroll
    for (int i = 0; i < 8; i++) {
        int m = m0 + ty * 8 + i;
        if (m >= M) continue;
        // precompute scatter targets for mode 2
        size_t r0 = 0, r1 = 0, r2 = 0, r3 = 0;
        if (mode == 2) {
            int b = m / Lseq, l = m % Lseq;
            int hg = l / WGc, wg = l % WGc;
            int j = wg * HGc + hg;
            size_t base = (size_t)b * Tseq;
            r0 = base + l;
            r1 = base + Lseq + j;
            r2 = base + 2 * Lseq + (Lseq - 1 - l);
            r3 = base + 3 * Lseq + (Lseq - 1 - j);
        }
        float* Crow = C + (size_t)m * ldc;
        const float* Rrow = resid ? resid + (size_t)m * ldc : (const float*)0;
#pragma unroll
        for (int g = 0; g < 2; g++) {
            int n = n0 + tx * 8 + g * 4;
            if (n >= N) continue;
            F4U o;
            o.u[0] = acc2[i][2 * g];
            o.u[1] = acc2[i][2 * g + 1];
            float4 v = o.f;
            if (bias) {
                float4 b4 = *(const float4*)(bias + n);
                v.x += b4.x; v.y += b4.y; v.z += b4.z; v.w += b4.w;
            }
            if (mode == 1) {
                v.x = 0.5f * v.x * (1.f + erff(v.x * 0.7071067811865475f));
                v.y = 0.5f * v.y * (1.f + erff(v.y * 0.7071067811865475f));
                v.z = 0.5f * v.z * (1.f + erff(v.z * 0.7071067811865475f));
                v.w = 0.5f * v.w * (1.f + erff(v.w * 0.7071067811865475f));
            }
            if (mode == 2) {
                *(float4*)(C + r0 * DMc + n) = v;
                *(float4*)(C + r1 * DMc + n) = v;
                *(float4*)(C + r2 * DMc + n) = v;
                *(float4*)(C + r3 * DMc + n) = v;
            } else {
                if (Rrow) {
                    float4 q4 = *(const float4*)(Rrow + n);
                    v.x += q4.x; v.y += q4.y; v.z += q4.z; v.w += q4.w;
                }
                *(float4*)(Crow + n) = v;
            }
        }
    }
}

// ---------------- patch gather ----------------
__global__ void patch_gather(const float* __restrict__ x)
{
    int idx = blockIdx.x * blockDim.x + threadIdx.x;
    if (idx >= NPATCH * PATCHK) return;
    int q  = idx % PATCHK;
    int bl = idx / PATCHK;
    int c  = q / 160, rr = q % 160;
    int i  = rr / PWc, jj = rr % PWc;
    int b  = bl / Lseq, l = bl % Lseq;
    int hg = l / WGc,  wg = l % WGc;
    g_patches[idx] = x[(((size_t)(b * CINc + c) * 340) + hg * PHc + i) * 720 + wg * PWc + jj];
}

// ---------------- rmsnorm over 128 channels ----------------
__global__ void rmsnorm128(const float* __restrict__ X, const float* __restrict__ w,
                           float* __restrict__ Y)
{
    int row = blockIdx.x;
    int tid = threadIdx.x;   // 128
    float v = X[(size_t)row * DMc + tid];
    float s = v * v;
#pragma unroll
    for (int o = 16; o > 0; o >>= 1) s += __shfl_xor_sync(0xffffffffu, s, o);
    __shared__ float ws[4];
    if ((tid & 31) == 0) ws[tid >> 5] = s;
    __syncthreads();
    float tot = ws[0] + ws[1] + ws[2] + ws[3];
    float sc = rsqrtf(tot * (1.f / DMc) + 1e-5f);
    Y[(size_t)row * DMc + tid] = v * sc * w[tid];
}

// ---------------- fused dt head: dt = softplus(hn.w_dt + b + dtb); dA ----------------
__global__ void dt_fused(const float* __restrict__ hn, const float* __restrict__ w,
                         const float* __restrict__ inb, const float* __restrict__ dtb,
                         const float* __restrict__ alog)
{
    int warp = (blockIdx.x * blockDim.x + threadIdx.x) >> 5;
    if (warp >= BT) return;
    int lane = threadIdx.x & 31;
    float4 hv = ((const float4*)(hn + (size_t)warp * DMc))[lane];
#pragma unroll
    for (int h = 0; h < 4; h++) {
        float4 wv = ((const float4*)(w + (size_t)(768 + h) * DMc))[lane];
        float d = hv.x * wv.x + hv.y * wv.y + hv.z * wv.z + hv.w * wv.w;
#pragma unroll
        for (int o = 16; o > 0; o >>= 1) d += __shfl_xor_sync(0xffffffffu, d, o);
        if (lane == 0) {
            float xv = d + inb[768 + h] + dtb[h];
            float sp = (xv > 20.f) ? xv : log1pf(expf(xv));
            g_dt[warp * 4 + h] = sp;
            g_dA[warp * 4 + h] = expf(-expf(alog[h]) * sp);
        }
    }
}

// ---------------- conv(K=4)+silu over 512 chans, fused dtx for x-part ----------------
__global__ void conv_silu(const float* __restrict__ cw, const float* __restrict__ cb)
{
    size_t idx = (size_t)blockIdx.x * blockDim.x + threadIdx.x;
    if (idx >= (size_t)BT * 512) return;
    int c  = (int)(idx & 511);
    int bt = (int)(idx >> 9);
    int t  = bt % Tseq;
    int b  = bt / Tseq;
    float acc = cb[c];
#pragma unroll
    for (int k = 0; k < 4; k++) {
        int tt = t + k - 3;
        if (tt >= 0)
            acc = fmaf(g_proj[((size_t)(b * Tseq + tt)) * PROJW + 256 + c], cw[c * 4 + k], acc);
    }
    float sg = 1.f / (1.f + expf(-acc));
    float val = acc * sg;
    g_xbc[idx] = val;
    if (c < 256)
        g_dtx[(size_t)bt * EXPC + c] = g_dt[bt * 4 + (c >> 6)] * val;
}

// ---------------- cumprod of dA within each segment (warp per (b,h,seg)) ----------------
__global__ void e_kernel()
{
    int gw   = blockIdx.x * 8 + (threadIdx.x >> 5);   // 0..255 = bh(32) x seg(8)
    int lane = threadIdx.x & 31;
    int bh = gw >> 3, seg = gw & 7;
    int b = bh >> 2, h = bh & 3;
    size_t dbase = ((size_t)b * Tseq + seg * QSEG) * 4 + h;
    float v[24];
    float prod = 1.f;
#pragma unroll
    for (int i = 0; i < 24; i++) {
        int t = lane * 24 + i;
        float d = (t < QSEG) ? g_dA[dbase + (size_t)t * 4] : 1.f;
        prod *= d;
        v[i] = prod;
    }
    // inclusive multiply-scan of per-lane products
    float inc = prod;
#pragma unroll
    for (int o = 1; o < 32; o <<= 1) {
        float q = __shfl_up_sync(0xffffffffu, inc, o);
        if (lane >= o) inc *= q;
    }
    float exs = __shfl_up_sync(0xffffffffu, inc, 1);
    if (lane == 0) exs = 1.f;
    size_t ebase = (size_t)bh * Tseq + seg * QSEG;
#pragma unroll
    for (int i = 0; i < 24; i++) {
        int t = lane * 24 + i;
        if (t < QSEG) g_e[ebase + t] = exs * v[i];
    }
}

// ---------------- phase 1: partial scans per segment (from zero state) ----------------
__global__ __launch_bounds__(128)
void scan_partial()
{
    int bid  = blockIdx.x;            // 2048
    int b    = bid >> 8;
    int h    = (bid >> 6) & 3;
    int seg  = (bid >> 3) & 7;
    int pb   = bid & 7;
    int widx = threadIdx.x >> 5;
    int lane = threadIdx.x & 31;
    int p    = pb * 8 + widx * 2;
    int t0   = seg * QSEG;

    const float*  dAp = g_dA + ((size_t)b * Tseq + t0) * NHC + h;
    const float2* dxp = (const float2*)(g_dtx + ((size_t)b * Tseq + t0) * EXPC + h * HDC + p);
    const float4* B4  = (const float4*)(g_xbc + ((size_t)b * Tseq + t0) * 512 + 256);
    const float4* C4  = (const float4*)(g_xbc + ((size_t)b * Tseq + t0) * 512 + 384);
    float* yp = g_y + ((size_t)b * Tseq + t0) * EXPC + h * HDC + p + (lane >> 4);
    bool doStore = ((lane & 15) == 0);

    float4 s0 = make_float4(0.f, 0.f, 0.f, 0.f);
    float4 s1 = make_float4(0.f, 0.f, 0.f, 0.f);
    float4 bv = B4[lane], cv = C4[lane];
    float  da = dAp[0];
    float2 xx = dxp[0];
    for (int t = 0; t < QSEG; t++) {
        float4 bn = bv, cn = cv;
        float d0 = da; float2 x0 = xx;
        if (t + 1 < QSEG) {
            size_t o4 = (size_t)(t + 1) * 128 + lane;
            bv = B4[o4]; cv = C4[o4];
            da = dAp[(size_t)(t + 1) * NHC];
            xx = dxp[(size_t)(t + 1) * (EXPC / 2)];
        }
        s0.x = fmaf(s0.x, d0, x0.x * bn.x);
        s0.y = fmaf(s0.y, d0, x0.x * bn.y);
        s0.z = fmaf(s0.z, d0, x0.x * bn.z);
        s0.w = fmaf(s0.w, d0, x0.x * bn.w);
        s1.x = fmaf(s1.x, d0, x0.y * bn.x);
        s1.y = fmaf(s1.y, d0, x0.y * bn.y);
        s1.z = fmaf(s1.z, d0, x0.y * bn.z);
        s1.w = fmaf(s1.w, d0, x0.y * bn.w);
        float a0 = s0.x * cn.x + s0.y * cn.y + s0.z * cn.z + s0.w * cn.w;
        float a1 = s1.x * cn.x + s1.y * cn.y + s1.z * cn.z + s1.w * cn.w;
        float u = a0 + __shfl_xor_sync(0xffffffffu, a0, 16);
        float v = a1 + __shfl_xor_sync(0xffffffffu, a1, 16);
        float w = (lane & 16) ? v : u;
        w += __shfl_xor_sync(0xffffffffu, w, 8);
        w += __shfl_xor_sync(0xffffffffu, w, 4);
        w += __shfl_xor_sync(0xffffffffu, w, 2);
        w += __shfl_xor_sync(0xffffffffu, w, 1);
        if (doStore) yp[(size_t)t * EXPC] = w;
    }
    // store segment-final partial state: layout [(bh*SEGS+seg)*64 + p][n]
    int bh = b * 4 + h;
    ((float4*)(g_spart + (((size_t)bh * SEGS + seg) * 64 + p) * 128))[lane] = s0;
    ((float4*)(g_spart + (((size_t)bh * SEGS + seg) * 64 + p + 1) * 128))[lane] = s1;
}

// ---------------- phase 2: carry initial states across segments ----------------
__global__ void carry_kernel()
{
    int bh = blockIdx.x;       // 32 blocks
    int tid = threadIdx.x;     // 256
    __shared__ float Ps[SEGS];
    if (tid < SEGS) Ps[tid] = g_e[(size_t)bh * Tseq + (size_t)(tid + 1) * QSEG - 1];
    __syncthreads();
    for (int k = 0; k < 32; k++) {
        int idx = tid + k * 256;  // p*128+n
        float sini = 0.f;
#pragma unroll
        for (int s = 1; s < SEGS; s++) {
            sini = g_spart[((size_t)bh * SEGS + (s - 1)) * 8192 + idx] + sini * Ps[s - 1];
            g_sinit[((size_t)bh * SEGS + s) * 8192 + idx] = sini;
        }
    }
}

// ---------------- phase 3: y[t,p] += e_t * (C_t . S_init)  (128x64xK128 GEMM) ----------------
__global__ __launch_bounds__(256)
void corr_kernel()
{
    int mt  = blockIdx.x;            // 0..5
    int seg = blockIdx.y + 1;        // 1..7
    int bh  = blockIdx.z;            // 0..31
    int b = bh >> 2, h = bh & 3;
    int t0 = seg * QSEG + mt * 128;  // global t of first row
    // exact early exit: e monotone decreasing within segment; 0 => all later 0
    if (g_e[(size_t)bh * Tseq + t0] == 0.f) return;

    __shared__ __align__(16) float Cs[BK][BM + 4];
    __shared__ __align__(16) float Ss[BK][68];
    const int tid = threadIdx.x;
    const int tx = tid & 15;   // p: 4 each
    const int ty = tid >> 4;   // t: 8 each
    const int lr = tid >> 2;
    const int lc = (tid & 3) << 2;

    const float* Abase = g_xbc + ((size_t)(b * Tseq + t0)) * 512 + 384;
    const float* Sbase = g_sinit + ((size_t)bh * SEGS + seg) * 8192;
    float acc[8][4];
#pragma unroll
    for (int i = 0; i < 8; i++)
#pragma unroll
        for (int j = 0; j < 4; j++) acc[i][j] = 0.f;

    const int mlim = QSEG - mt * 128;   // valid local rows
    for (int k0 = 0; k0 < 128; k0 += BK) {
        // load C rows (128 x 16)
        float4 va = (lr < mlim) ? *(const float4*)(Abase + (size_t)lr * 512 + k0 + lc)
                                : make_float4(0.f, 0.f, 0.f, 0.f);
        float4 vb = (lr + 64 < mlim) ? *(const float4*)(Abase + (size_t)(lr + 64) * 512 + k0 + lc)
                                     : make_float4(0.f, 0.f, 0.f, 0.f);
        float4 vs = *(const float4*)(Sbase + (size_t)lr * 128 + k0 + lc);
        __syncthreads();
        Cs[lc + 0][lr] = va.x; Cs[lc + 1][lr] = va.y; Cs[lc + 2][lr] = va.z; Cs[lc + 3][lr] = va.w;
        Cs[lc + 0][lr + 64] = vb.x; Cs[lc + 1][lr + 64] = vb.y;
        Cs[lc + 2][lr + 64] = vb.z; Cs[lc + 3][lr + 64] = vb.w;
        Ss[lc + 0][lr] = vs.x; Ss[lc + 1][lr] = vs.y; Ss[lc + 2][lr] = vs.z; Ss[lc + 3][lr] = vs.w;
        __syncthreads();
#pragma unroll
        for (int kk = 0; kk < BK; kk++) {
            float4 a0 = *(const float4*)&Cs[kk][ty * 8];
            float4 a1 = *(const float4*)&Cs[kk][ty * 8 + 4];
            float4 bq = *(const float4*)&Ss[kk][tx * 4];
            float av[8] = {a0.x, a0.y, a0.z, a0.w, a1.x, a1.y, a1.z, a1.w};
            float bw[4] = {bq.x, bq.y, bq.z, bq.w};
#pragma unroll
            for (int i = 0; i < 8; i++)
#pragma unroll
                for (int j = 0; j < 4; j++)
                    acc[i][j] = fmaf(av[i], bw[j], acc[i][j]);
        }
    }
#pragma unroll
    for (int i = 0; i < 8; i++) {
        int mrow = ty * 8 + i;
        if (mrow >= mlim) continue;
        int tg = t0 + mrow;
        float e = g_e[(size_t)bh * Tseq + tg];
        float* yd = g_y + ((size_t)(b * Tseq + tg)) * EXPC + h * 64 + tx * 4;
        float4 old = *(float4*)yd;
        old.x += e * acc[i][0];
        old.y += e * acc[i][1];
        old.z += e * acc[i][2];
        old.w += e * acc[i][3];
        *(float4*)yd = old;
    }
}

// ---------------- (y + D*x) * silu(gate), rmsnorm(256) with gn_w ----------------
__global__ void gate_norm(const float* __restrict__ Dp, const float* __restrict__ gnw)
{
    int row = blockIdx.x;
    int tid = threadIdx.x;   // 256
    float xh = g_xbc[(size_t)row * 512 + tid];
    float yv = g_y[(size_t)row * EXPC + tid] + Dp[tid >> 6] * xh;
    float g  = g_proj[(size_t)row * PROJW + tid];
    float v  = yv * (g / (1.f + expf(-g)));
    float s = v * v;
#pragma unroll
    for (int o = 16; o > 0; o >>= 1) s += __shfl_xor_sync(0xffffffffu, s, o);
    __shared__ float ws[8];
    if ((tid & 31) == 0) ws[tid >> 5] = s;
    __syncthreads();
    float tot = 0.f;
#pragma unroll
    for (int i = 0; i < 8; i++) tot += ws[i];
    float sc = rsqrtf(tot * (1.f / EXPC) + 1e-5f);
    g_z[(size_t)row * EXPC + tid] = v * sc * gnw[tid];
}

// ---------------- combine the 4 directional outputs back to (B,L,DM) ----------------
__global__ void combine_kernel()
{
    int bl = blockIdx.x;
    int b = bl / Lseq, l = bl % Lseq;
    int hg = l / WGc, wg = l % WGc;
    int j = wg * HGc + hg;
    int tid = threadIdx.x;
    size_t base = (size_t)b * Tseq;
    float v = g_hn[(base + l) * DMc + tid]
            + g_hn[(base + Lseq + j) * DMc + tid]
            + g_hn[(base + 2 * Lseq + (Lseq - 1 - l)) * DMc + tid]
            + g_hn[(base + 3 * Lseq + (Lseq - 1 - j)) * DMc + tid];
    g_xm[(size_t)bl * DMc + tid] = v;
}

// ---------------- unpatchify to (B,CIN,340,720) ----------------
__global__ void unpatch(float* __restrict__ out)
{
    int idx = blockIdx.x * blockDim.x + threadIdx.x;
    if (idx >= NPATCH * PATCHK) return;
    int xc = idx % 720;
    int t1 = idx / 720;
    int y  = t1 % 340;
    int t2 = t1 / 340;
    int c  = t2 % 3;
    int b  = t2 / 3;
    int hg = y / PHc,  i  = y % PHc;
    int wg = xc / PWc, jj = xc % PWc;
    int l  = hg * WGc + wg;
    out[idx] = g_proj[((size_t)(b * Lseq + l)) * 480 + i * 24 + jj * 3 + c];
}

// ---------------- host orchestration ----------------
static float* sym_addr(const void* sym)
{
    void* p = nullptr;
    cudaGetSymbolAddress(&p, sym);
    return (float*)p;
}

extern "C" void kernel_launch(void* const* d_in, const int* in_sizes, int n_in,
                              void* d_out, int out_size)
{
    (void)in_sizes; (void)n_in; (void)out_size;
    const float* x       = (const float*)d_in[0];
    const float* W_pe    = (const float*)d_in[1];
    const float* b_pe    = (const float*)d_in[2];
    const float* norm_w  = (const float*)d_in[3];
    const float* in_w    = (const float*)d_in[4];
    const float* in_b    = (const float*)d_in[5];
    const float* conv_w  = (const float*)d_in[6];
    const float* conv_b  = (const float*)d_in[7];
    const float* dt_bias = (const float*)d_in[8];
    const float* A_log   = (const float*)d_in[9];
    const float* Dp      = (const float*)d_in[10];
    const float* gn_w    = (const float*)d_in[11];
    const float* out_w   = (const float*)d_in[12];
    const float* out_b   = (const float*)d_in[13];
    const float* normf_w = (const float*)d_in[14];
    const float* r1_w    = (const float*)d_in[15];
    const float* r1_b    = (const float*)d_in[16];
    const float* r2_w    = (const float*)d_in[17];
    const float* r2_b    = (const float*)d_in[18];
    float* out = (float*)d_out;

    float* patches = sym_addr(g_patches);
    float* emb     = sym_addr(g_emb);
    float* hbuf    = sym_addr(g_h);
    float* hn      = sym_addr(g_hn);
    float* proj    = sym_addr(g_proj);
    float* zbuf    = sym_addr(g_z);
    float* xm      = sym_addr(g_xm);

    // 1: patch gather, 2: patch-embed GEMM with fused 4-direction scatter into g_h
    patch_gather<<<(NPATCH * PATCHK + 255) / 256, 256>>>(x);
    gemm128<<<dim3(1, (NPATCH + BM - 1) / BM), 256>>>(patches, W_pe, b_pe, nullptr,
                                                      hbuf, NPATCH, DMc, PATCHK, DMc, 2);

    for (int l = 0; l < 4; l++) {
        const float* iw = in_w + (size_t)l * 772 * DMc;
        const float* ib = in_b + (size_t)l * 772;
        rmsnorm128<<<BT, 128>>>(hbuf, norm_w + l * DMc, hn);
        gemm128<<<dim3(PROJW / BN, (BT + BM - 1) / BM), 256>>>(
            hn, iw, ib, nullptr, proj, BT, PROJW, DMc, PROJW, 0);
        dt_fused<<<BT / 8, 256>>>(hn, iw, ib, dt_bias + l * NHC, A_log + l * NHC);
        conv_silu<<<(int)(((size_t)BT * 512 + 255) / 256), 256>>>(
            conv_w + l * 512 * 4, conv_b + l * 512);
        e_kernel<<<32, 256>>>();
        scan_partial<<<2048, 128>>>();
        carry_kernel<<<32, 256>>>();
        corr_kernel<<<dim3(6, SEGS - 1, 32), 256>>>();
        gate_norm<<<BT, 256>>>(Dp + l * NHC, gn_w + l * EXPC);
        gemm128<<<dim3(1, (BT + BM - 1) / BM), 256>>>(
            zbuf, out_w + (size_t)l * DMc * EXPC, out_b + l * DMc, hbuf,
            hbuf, BT, DMc, EXPC, DMc, 0);
    }

    rmsnorm128<<<BT, 128>>>(hbuf, normf_w, hn);
    combine_kernel<<<NPATCH, 128>>>();
    gemm128<<<dim3(1, (NPATCH + BM - 1) / BM), 256>>>(xm, r1_w, r1_b, nullptr,
                                                      emb, NPATCH, DMc, DMc, DMc, 1);
    gemm128<<<dim3((480 + BN - 1) / BN, (NPATCH + BM - 1) / BM), 256>>>(
        emb, r2_w, r2_b, nullptr, proj, NPATCH, 480, DMc, 480, 0);
    unpatch<<<(NPATCH * PATCHK + 255) / 256, 256>>>(out);
}

// round 5
// speedup vs baseline: 3.0079x; 1.1994x over previous
#include <cuda_runtime.h>
#include <cuda_bf16.h>
#include <math.h>
#include <stdint.h>

// ---------------- problem constants ----------------
#define BATCH  8
#define HGc    17
#define WGc    90
#define Lseq   1530            // HG*WG
#define Tseq   6120            // 4*L
#define BT     48960           // BATCH*Tseq
#define DMc    128
#define EXPC   256
#define NHC    4
#define HDC    64
#define PHc    20
#define PWc    8
#define CINc   3
#define PATCHK 480             // CIN*PH*PW
#define NPATCH 12240           // BATCH*Lseq
#define PROJW  768             // gate(256)+xBC(512); dt handled separately
#define SEGS   8
#define QSEG   765             // Tseq / SEGS

// ---------------- device scratch (static, no allocs) ----------------
__device__ float g_patches[(size_t)NPATCH * PATCHK];
__device__ float g_emb    [(size_t)NPATCH * DMc];      // reused as MLP hidden
__device__ float g_h      [(size_t)BT * DMc];
__device__ float g_hn     [(size_t)BT * DMc];
__device__ float g_proj   [(size_t)BT * PROJW];        // reused as final r output
__device__ float g_xbc    [(size_t)BT * 512];
__device__ float g_dt     [(size_t)BT * NHC];
__device__ float g_dA     [(size_t)BT * NHC];
__device__ float g_dtx    [(size_t)BT * EXPC];
__device__ float g_y      [(size_t)BT * EXPC];
__device__ float g_xm     [(size_t)NPATCH * DMc];
__device__ float g_e      [(size_t)32 * Tseq];                 // cumprod dA per (b,h)
__device__ float g_spart  [(size_t)32 * SEGS * 64 * 128];      // segment-final partial states
__device__ float g_sinit  [(size_t)32 * SEGS * 64 * 128];      // segment initial states
// bf16 split operand buffers for tensor-core GEMMs
__device__ __nv_bfloat16 g_ahi[(size_t)BT * 256];
__device__ __nv_bfloat16 g_alo[(size_t)BT * 256];
__device__ __nv_bfloat16 g_whi[(size_t)768 * 256];
__device__ __nv_bfloat16 g_wlo[(size_t)768 * 256];

__device__ __forceinline__ uint32_t smem_u32(const void* p)
{
    uint32_t a;
    asm("{ .reg .u64 t; cvta.to.shared.u64 t, %1; cvt.u32.u64 %0, t; }"
        : "=r"(a) : "l"(p));
    return a;
}

__device__ __forceinline__ void ldmx4(uint32_t& r0, uint32_t& r1, uint32_t& r2,
                                      uint32_t& r3, uint32_t addr)
{
    asm volatile("ldmatrix.sync.aligned.m8n8.x4.shared.b16 {%0,%1,%2,%3}, [%4];"
                 : "=r"(r0), "=r"(r1), "=r"(r2), "=r"(r3) : "r"(addr));
}

__device__ __forceinline__ void mma_bf16(float* d, const uint32_t* a, const uint32_t* b)
{
    asm volatile(
        "mma.sync.aligned.m16n8k16.row.col.f32.bf16.bf16.f32 "
        "{%0,%1,%2,%3}, {%4,%5,%6,%7}, {%8,%9}, {%0,%1,%2,%3};"
        : "+f"(d[0]), "+f"(d[1]), "+f"(d[2]), "+f"(d[3])
        : "r"(a[0]), "r"(a[1]), "r"(a[2]), "r"(a[3]), "r"(b[0]), "r"(b[1]));
}

// ---------------- bf16-split tensor-core GEMM (mma.sync) ----------------
// C[M,N](ld=ldc) = A @ W^T + bias (+resid), A=(Ahi+Alo)[M,K], W=(Whi+Wlo)[N,K]
// 128x128 tile, 8 warps (2x4), k-chunk 64. K % 64 == 0. N tiles fully valid
// when N % 128 == 0; partial-N guarded.
#define MLDS 72   // smem row pitch in bf16 (144 bytes -> ldmatrix conflict-free)

__global__ __launch_bounds__(256)
void mma_gemm(const __nv_bfloat16* __restrict__ Ahi, const __nv_bfloat16* __restrict__ Alo,
              const __nv_bfloat16* __restrict__ Whi, const __nv_bfloat16* __restrict__ Wlo,
              const float* __restrict__ bias, const float* __restrict__ resid,
              float* __restrict__ C, int M, int Ktot, int N, int ldc)
{
    extern __shared__ __align__(16) __nv_bfloat16 sm[];
    __nv_bfloat16* sAh = sm;
    __nv_bfloat16* sAl = sAh + 128 * MLDS;
    __nv_bfloat16* sWh = sAl + 128 * MLDS;
    __nv_bfloat16* sWl = sWh + 128 * MLDS;
    const uint32_t bAh = smem_u32(sAh);
    const uint32_t bAl = smem_u32(sAl);
    const uint32_t bWh = smem_u32(sWh);
    const uint32_t bWl = smem_u32(sWl);

    const int tid  = threadIdx.x;
    const int wid  = tid >> 5;
    const int lane = tid & 31;
    const int m0 = blockIdx.y * 128;
    const int n0 = blockIdx.x * 128;
    const int wm = (wid >> 2) * 64;   // warp M offset in tile
    const int wn = (wid & 3) * 32;    // warp N offset in tile

    float acc[4][4][4];
#pragma unroll
    for (int i = 0; i < 4; i++)
#pragma unroll
        for (int j = 0; j < 4; j++)
#pragma unroll
            for (int q = 0; q < 4; q++) acc[i][j][q] = 0.f;

    const int lrow = tid >> 1;          // 0..127
    const int lcol = (tid & 1) * 32;    // 0 or 32
    const bool okA = (m0 + lrow) < M;
    const bool okW = (n0 + lrow) < N;
    const uint4 z16 = make_uint4(0u, 0u, 0u, 0u);

    // per-lane ldmatrix byte offsets
    const int lm_row = lane & 15;
    const int lm_col = (lane >> 4) * 8;

    for (int kc = 0; kc < Ktot; kc += 64) {
        if (kc) __syncthreads();
        const uint4* pAh = (const uint4*)(Ahi + (size_t)(m0 + lrow) * Ktot + kc + lcol);
        const uint4* pAl = (const uint4*)(Alo + (size_t)(m0 + lrow) * Ktot + kc + lcol);
        const uint4* pWh = (const uint4*)(Whi + (size_t)(n0 + lrow) * Ktot + kc + lcol);
        const uint4* pWl = (const uint4*)(Wlo + (size_t)(n0 + lrow) * Ktot + kc + lcol);
        uint4* dAh = (uint4*)(sAh + lrow * MLDS + lcol);
        uint4* dAl = (uint4*)(sAl + lrow * MLDS + lcol);
        uint4* dWh = (uint4*)(sWh + lrow * MLDS + lcol);
        uint4* dWl = (uint4*)(sWl + lrow * MLDS + lcol);
#pragma unroll
        for (int q = 0; q < 4; q++) {
            dAh[q] = okA ? pAh[q] : z16;
            dAl[q] = okA ? pAl[q] : z16;
            dWh[q] = okW ? pWh[q] : z16;
            dWl[q] = okW ? pWl[q] : z16;
        }
        __syncthreads();

#pragma unroll
        for (int ks = 0; ks < 4; ks++) {
            const int k0 = ks * 16;
            // B fragments: 4 n-tiles (hi & lo)
            uint32_t bh[4][2], bl[4][2];
#pragma unroll
            for (int pr = 0; pr < 2; pr++) {
                uint32_t off = (uint32_t)(((wn + pr * 16 + lm_row) * MLDS + k0 + lm_col) * 2);
                uint32_t r0, r1, r2, r3;
                ldmx4(r0, r1, r2, r3, bWh + off);
                bh[pr * 2][0] = r0; bh[pr * 2 + 1][0] = r1;
                bh[pr * 2][1] = r2; bh[pr * 2 + 1][1] = r3;
                ldmx4(r0, r1, r2, r3, bWl + off);
                bl[pr * 2][0] = r0; bl[pr * 2 + 1][0] = r1;
                bl[pr * 2][1] = r2; bl[pr * 2 + 1][1] = r3;
            }
#pragma unroll
            for (int mt = 0; mt < 4; mt++) {
                uint32_t off = (uint32_t)(((wm + mt * 16 + lm_row) * MLDS + k0 + lm_col) * 2);
                uint32_t ah[4], al[4];
                ldmx4(ah[0], ah[1], ah[2], ah[3], bAh + off);
                ldmx4(al[0], al[1], al[2], al[3], bAl + off);
#pragma unroll
                for (int nt = 0; nt < 4; nt++) {
                    mma_bf16(acc[mt][nt], ah, bh[nt]);
                    mma_bf16(acc[mt][nt], ah, bl[nt]);
                    mma_bf16(acc[mt][nt], al, bh[nt]);
                }
            }
        }
    }

    // epilogue
    const int gid = lane >> 2;
    const int tig = lane & 3;
#pragma unroll
    for (int mt = 0; mt < 4; mt++) {
        int row0 = m0 + wm + mt * 16 + gid;
        int row1 = row0 + 8;
#pragma unroll
        for (int nt = 0; nt < 4; nt++) {
            int col = n0 + wn + nt * 8 + tig * 2;
            if (col >= N) continue;
            float bx = bias ? bias[col] : 0.f;
            float by = bias ? bias[col + 1] : 0.f;
            if (row0 < M) {
                float2 v = make_float2(acc[mt][nt][0] + bx, acc[mt][nt][1] + by);
                if (resid) {
                    float2 r = *(const float2*)(resid + (size_t)row0 * ldc + col);
                    v.x += r.x; v.y += r.y;
                }
                *(float2*)(C + (size_t)row0 * ldc + col) = v;
            }
            if (row1 < M) {
                float2 v = make_float2(acc[mt][nt][2] + bx, acc[mt][nt][3] + by);
                if (resid) {
                    float2 r = *(const float2*)(resid + (size_t)row1 * ldc + col);
                    v.x += r.x; v.y += r.y;
                }
                *(float2*)(C + (size_t)row1 * ldc + col) = v;
            }
        }
    }
}
#define MMA_SMEM (4 * 128 * MLDS * 2)

// ---------------- weight fp32 -> bf16 hi/lo split ----------------
__global__ void wconv(const float* __restrict__ w, int total)
{
    int idx = blockIdx.x * blockDim.x + threadIdx.x;
    if (idx >= total) return;
    float v = w[idx];
    __nv_bfloat16 hi = __float2bfloat16(v);
    g_whi[idx] = hi;
    g_wlo[idx] = __float2bfloat16(v - __bfloat162float(hi));
}

// =================================================================
//                fp32 f32x2 GEMM (small GEMMs)
// =================================================================
union F4U { float4 f; unsigned long long u[2]; };

__device__ __forceinline__ unsigned long long ffma2(unsigned long long a,
                                                    unsigned long long b,
                                                    unsigned long long c)
{
    unsigned long long d;
    asm("fma.rn.f32x2 %0, %1, %2, %3;" : "=l"(d) : "l"(a), "l"(b), "l"(c));
    return d;
}

#define BM 128
#define BN 128
#define BK 16

__global__ __launch_bounds__(256, 2)
void gemm128(const float* __restrict__ A, const float* __restrict__ W,
             const float* __restrict__ bias, const float* __restrict__ resid,
             float* __restrict__ C, int M, int N, int K, int ldc, int mode)
{
    __shared__ __align__(16) float As[2][BK][2 * BM];   // duplicated A
    __shared__ __align__(16) float Bs[2][BK][BN];
    const int tid = threadIdx.x;
    const int m0 = blockIdx.y * BM;
    const int n0 = blockIdx.x * BN;
    const int lr = tid >> 2;
    const int lc = (tid & 3) << 2;
    const int tx = tid & 15;
    const int ty = tid >> 4;

    const int mA0 = m0 + lr, mA1 = m0 + lr + 64;
    const int nB0 = n0 + lr, nB1 = n0 + lr + 64;
    const bool okA0 = mA0 < M, okA1 = mA1 < M;
    const bool okB0 = nB0 < N, okB1 = nB1 < N;
    const float4 z4 = make_float4(0.f, 0.f, 0.f, 0.f);

    unsigned long long acc2[8][4];
#pragma unroll
    for (int i = 0; i < 8; i++)
#pragma unroll
        for (int j = 0; j < 4; j++) acc2[i][j] = 0ull;

    float4 ra0 = okA0 ? *(const float4*)(A + (size_t)mA0 * K + lc) : z4;
    float4 ra1 = okA1 ? *(const float4*)(A + (size_t)mA1 * K + lc) : z4;
    float4 rb0 = okB0 ? *(const float4*)(W + (size_t)nB0 * K + lc) : z4;
    float4 rb1 = okB1 ? *(const float4*)(W + (size_t)nB1 * K + lc) : z4;
    {
        float a0[4] = {ra0.x, ra0.y, ra0.z, ra0.w};
        float a1[4] = {ra1.x, ra1.y, ra1.z, ra1.w};
        float b0[4] = {rb0.x, rb0.y, rb0.z, rb0.w};
        float b1[4] = {rb1.x, rb1.y, rb1.z, rb1.w};
#pragma unroll
        for (int q = 0; q < 4; q++) {
            As[0][lc + q][2 * lr] = a0[q];  As[0][lc + q][2 * lr + 1] = a0[q];
            As[0][lc + q][2 * (lr + 64)] = a1[q];  As[0][lc + q][2 * (lr + 64) + 1] = a1[q];
            Bs[0][lc + q][lr] = b0[q];
            Bs[0][lc + q][lr + 64] = b1[q];
        }
    }

    const int nch = K / BK;
    int buf = 0;
    for (int ch = 0; ch < nch; ch++) {
        __syncthreads();
        if (ch + 1 < nch) {
            int kof = (ch + 1) * BK + lc;
            ra0 = okA0 ? *(const float4*)(A + (size_t)mA0 * K + kof) : z4;
            ra1 = okA1 ? *(const float4*)(A + (size_t)mA1 * K + kof) : z4;
            rb0 = okB0 ? *(const float4*)(W + (size_t)nB0 * K + kof) : z4;
            rb1 = okB1 ? *(const float4*)(W + (size_t)nB1 * K + kof) : z4;
        }
#pragma unroll
        for (int kk = 0; kk < BK; kk++) {
            F4U ad0, ad1, ad2, ad3, bb0, bb1;
            ad0.f = *(const float4*)&As[buf][kk][(ty * 8 + 0) * 2];
            ad1.f = *(const float4*)&As[buf][kk][(ty * 8 + 2) * 2];
            ad2.f = *(const float4*)&As[buf][kk][(ty * 8 + 4) * 2];
            ad3.f = *(const float4*)&As[buf][kk][(ty * 8 + 6) * 2];
            bb0.f = *(const float4*)&Bs[buf][kk][tx * 8];
            bb1.f = *(const float4*)&Bs[buf][kk][tx * 8 + 4];
            unsigned long long ap[8] = {ad0.u[0], ad0.u[1], ad1.u[0], ad1.u[1],
                                        ad2.u[0], ad2.u[1], ad3.u[0], ad3.u[1]};
            unsigned long long bp[4] = {bb0.u[0], bb0.u[1], bb1.u[0], bb1.u[1]};
#pragma unroll
            for (int i = 0; i < 8; i++)
#pragma unroll
                for (int j = 0; j < 4; j++)
                    acc2[i][j] = ffma2(ap[i], bp[j], acc2[i][j]);
        }
        if (ch + 1 < nch) {
            int nb = buf ^ 1;
            float a0[4] = {ra0.x, ra0.y, ra0.z, ra0.w};
            float a1[4] = {ra1.x, ra1.y, ra1.z, ra1.w};
            float b0[4] = {rb0.x, rb0.y, rb0.z, rb0.w};
            float b1[4] = {rb1.x, rb1.y, rb1.z, rb1.w};
#pragma unroll
            for (int q = 0; q < 4; q++) {
                As[nb][lc + q][2 * lr] = a0[q];  As[nb][lc + q][2 * lr + 1] = a0[q];
                As[nb][lc + q][2 * (lr + 64)] = a1[q];  As[nb][lc + q][2 * (lr + 64) + 1] = a1[q];
                Bs[nb][lc + q][lr] = b0[q];
                Bs[nb][lc + q][lr + 64] = b1[q];
            }
        }
        buf ^= 1;
    }

#pragma unroll
    for (int i = 0; i < 8; i++) {
        int m = m0 + ty * 8 + i;
        if (m >= M) continue;
        size_t r0 = 0, r1 = 0, r2 = 0, r3 = 0;
        if (mode == 2) {
            int b = m / Lseq, l = m % Lseq;
            int hg = l / WGc, wg = l % WGc;
            int j = wg * HGc + hg;
            size_t base = (size_t)b * Tseq;
            r0 = base + l;
            r1 = base + Lseq + j;
            r2 = base + 2 * Lseq + (Lseq - 1 - l);
            r3 = base + 3 * Lseq + (Lseq - 1 - j);
        }
        float* Crow = C + (size_t)m * ldc;
        const float* Rrow = resid ? resid + (size_t)m * ldc : (const float*)0;
#pragma unroll
        for (int g = 0; g < 2; g++) {
            int n = n0 + tx * 8 + g * 4;
            if (n >= N) continue;
            F4U o;
            o.u[0] = acc2[i][2 * g];
            o.u[1] = acc2[i][2 * g + 1];
            float4 v = o.f;
            if (bias) {
                float4 b4 = *(const float4*)(bias + n);
                v.x += b4.x; v.y += b4.y; v.z += b4.z; v.w += b4.w;
            }
            if (mode == 1) {
                v.x = 0.5f * v.x * (1.f + erff(v.x * 0.7071067811865475f));
                v.y = 0.5f * v.y * (1.f + erff(v.y * 0.7071067811865475f));
                v.z = 0.5f * v.z * (1.f + erff(v.z * 0.7071067811865475f));
                v.w = 0.5f * v.w * (1.f + erff(v.w * 0.7071067811865475f));
            }
            if (mode == 2) {
                *(float4*)(C + r0 * DMc + n) = v;
                *(float4*)(C + r1 * DMc + n) = v;
                *(float4*)(C + r2 * DMc + n) = v;
                *(float4*)(C + r3 * DMc + n) = v;
            } else {
                if (Rrow) {
                    float4 q4 = *(const float4*)(Rrow + n);
                    v.x += q4.x; v.y += q4.y; v.z += q4.z; v.w += q4.w;
                }
                *(float4*)(Crow + n) = v;
            }
        }
    }
}

// ---------------- patch gather ----------------
__global__ void patch_gather(const float* __restrict__ x)
{
    int idx = blockIdx.x * blockDim.x + threadIdx.x;
    if (idx >= NPATCH * PATCHK) return;
    int q  = idx % PATCHK;
    int bl = idx / PATCHK;
    int c  = q / 160, rr = q % 160;
    int i  = rr / PWc, jj = rr % PWc;
    int b  = bl / Lseq, l = bl % Lseq;
    int hg = l / WGc,  wg = l % WGc;
    g_patches[idx] = x[(((size_t)(b * CINc + c) * 340) + hg * PHc + i) * 720 + wg * PWc + jj];
}

// ---------------- rmsnorm over 128 channels + optional bf16 split ----------------
__global__ void rmsnorm128(const float* __restrict__ X, const float* __restrict__ w,
                           float* __restrict__ Y, int emit_bf16)
{
    int row = blockIdx.x;
    int tid = threadIdx.x;   // 128
    float v = X[(size_t)row * DMc + tid];
    float s = v * v;
#pragma unroll
    for (int o = 16; o > 0; o >>= 1) s += __shfl_xor_sync(0xffffffffu, s, o);
    __shared__ float ws[4];
    if ((tid & 31) == 0) ws[tid >> 5] = s;
    __syncthreads();
    float tot = ws[0] + ws[1] + ws[2] + ws[3];
    float sc = rsqrtf(tot * (1.f / DMc) + 1e-5f);
    float outv = v * sc * w[tid];
    Y[(size_t)row * DMc + tid] = outv;
    if (emit_bf16) {
        __nv_bfloat16 hi = __float2bfloat16(outv);
        g_ahi[(size_t)row * DMc + tid] = hi;
        g_alo[(size_t)row * DMc + tid] = __float2bfloat16(outv - __bfloat162float(hi));
    }
}

// ---------------- fused dt head: dt = softplus(hn.w_dt + b + dtb); dA ----------------
__global__ void dt_fused(const float* __restrict__ hn, const float* __restrict__ w,
                         const float* __restrict__ inb, const float* __restrict__ dtb,
                         const float* __restrict__ alog)
{
    int warp = (blockIdx.x * blockDim.x + threadIdx.x) >> 5;
    if (warp >= BT) return;
    int lane = threadIdx.x & 31;
    float4 hv = ((const float4*)(hn + (size_t)warp * DMc))[lane];
#pragma unroll
    for (int h = 0; h < 4; h++) {
        float4 wv = ((const float4*)(w + (size_t)(768 + h) * DMc))[lane];
        float d = hv.x * wv.x + hv.y * wv.y + hv.z * wv.z + hv.w * wv.w;
#pragma unroll
        for (int o = 16; o > 0; o >>= 1) d += __shfl_xor_sync(0xffffffffu, d, o);
        if (lane == 0) {
            float xv = d + inb[768 + h] + dtb[h];
            float sp = (xv > 20.f) ? xv : log1pf(expf(xv));
            g_dt[warp * 4 + h] = sp;
            g_dA[warp * 4 + h] = expf(-expf(alog[h]) * sp);
        }
    }
}

// ---------------- conv(K=4)+silu over 512 chans, fused dtx for x-part ----------------
__global__ void conv_silu(const float* __restrict__ cw, const float* __restrict__ cb)
{
    size_t idx = (size_t)blockIdx.x * blockDim.x + threadIdx.x;
    if (idx >= (size_t)BT * 512) return;
    int c  = (int)(idx & 511);
    int bt = (int)(idx >> 9);
    int t  = bt % Tseq;
    int b  = bt / Tseq;
    float acc = cb[c];
#pragma unroll
    for (int k = 0; k < 4; k++) {
        int tt = t + k - 3;
        if (tt >= 0)
            acc = fmaf(g_proj[((size_t)(b * Tseq + tt)) * PROJW + 256 + c], cw[c * 4 + k], acc);
    }
    float sg = 1.f / (1.f + expf(-acc));
    float val = acc * sg;
    g_xbc[idx] = val;
    if (c < 256)
        g_dtx[(size_t)bt * EXPC + c] = g_dt[bt * 4 + (c >> 6)] * val;
}

// ---------------- cumprod of dA within each segment (warp per (b,h,seg)) ----------------
__global__ void e_kernel()
{
    int gw   = blockIdx.x * 8 + (threadIdx.x >> 5);   // 0..255 = bh(32) x seg(8)
    int lane = threadIdx.x & 31;
    int bh = gw >> 3, seg = gw & 7;
    int b = bh >> 2, h = bh & 3;
    size_t dbase = ((size_t)b * Tseq + seg * QSEG) * 4 + h;
    float v[24];
    float prod = 1.f;
#pragma unroll
    for (int i = 0; i < 24; i++) {
        int t = lane * 24 + i;
        float d = (t < QSEG) ? g_dA[dbase + (size_t)t * 4] : 1.f;
        prod *= d;
        v[i] = prod;
    }
    float inc = prod;
#pragma unroll
    for (int o = 1; o < 32; o <<= 1) {
        float q = __shfl_up_sync(0xffffffffu, inc, o);
        if (lane >= o) inc *= q;
    }
    float exs = __shfl_up_sync(0xffffffffu, inc, 1);
    if (lane == 0) exs = 1.f;
    size_t ebase = (size_t)bh * Tseq + seg * QSEG;
#pragma unroll
    for (int i = 0; i < 24; i++) {
        int t = lane * 24 + i;
        if (t < QSEG) g_e[ebase + t] = exs * v[i];
    }
}

// ---------------- phase 1: partial scans per segment (from zero state) ----------------
__global__ __launch_bounds__(128)
void scan_partial()
{
    int bid  = blockIdx.x;            // 2048
    int b    = bid >> 8;
    int h    = (bid >> 6) & 3;
    int seg  = (bid >> 3) & 7;
    int pb   = bid & 7;
    int widx = threadIdx.x >> 5;
    int lane = threadIdx.x & 31;
    int p    = pb * 8 + widx * 2;
    int t0   = seg * QSEG;

    const float*  dAp = g_dA + ((size_t)b * Tseq + t0) * NHC + h;
    const float2* dxp = (const float2*)(g_dtx + ((size_t)b * Tseq + t0) * EXPC + h * HDC + p);
    const float4* B4  = (const float4*)(g_xbc + ((size_t)b * Tseq + t0) * 512 + 256);
    const float4* C4  = (const float4*)(g_xbc + ((size_t)b * Tseq + t0) * 512 + 384);
    float* yp = g_y + ((size_t)b * Tseq + t0) * EXPC + h * HDC + p + (lane >> 4);
    bool doStore = ((lane & 15) == 0);

    float4 s0 = make_float4(0.f, 0.f, 0.f, 0.f);
    float4 s1 = make_float4(0.f, 0.f, 0.f, 0.f);
    float4 bv = B4[lane], cv = C4[lane];
    float  da = dAp[0];
    float2 xx = dxp[0];
    for (int t = 0; t < QSEG; t++) {
        float4 bn = bv, cn = cv;
        float d0 = da; float2 x0 = xx;
        if (t + 1 < QSEG) {
            size_t o4 = (size_t)(t + 1) * 128 + lane;
            bv = B4[o4]; cv = C4[o4];
            da = dAp[(size_t)(t + 1) * NHC];
            xx = dxp[(size_t)(t + 1) * (EXPC / 2)];
        }
        s0.x = fmaf(s0.x, d0, x0.x * bn.x);
        s0.y = fmaf(s0.y, d0, x0.x * bn.y);
        s0.z = fmaf(s0.z, d0, x0.x * bn.z);
        s0.w = fmaf(s0.w, d0, x0.x * bn.w);
        s1.x = fmaf(s1.x, d0, x0.y * bn.x);
        s1.y = fmaf(s1.y, d0, x0.y * bn.y);
        s1.z = fmaf(s1.z, d0, x0.y * bn.z);
        s1.w = fmaf(s1.w, d0, x0.y * bn.w);
        float a0 = s0.x * cn.x + s0.y * cn.y + s0.z * cn.z + s0.w * cn.w;
        float a1 = s1.x * cn.x + s1.y * cn.y + s1.z * cn.z + s1.w * cn.w;
        float u = a0 + __shfl_xor_sync(0xffffffffu, a0, 16);
        float v = a1 + __shfl_xor_sync(0xffffffffu, a1, 16);
        float w = (lane & 16) ? v : u;
        w += __shfl_xor_sync(0xffffffffu, w, 8);
        w += __shfl_xor_sync(0xffffffffu, w, 4);
        w += __shfl_xor_sync(0xffffffffu, w, 2);
        w += __shfl_xor_sync(0xffffffffu, w, 1);
        if (doStore) yp[(size_t)t * EXPC] = w;
    }
    int bh = b * 4 + h;
    ((float4*)(g_spart + (((size_t)bh * SEGS + seg) * 64 + p) * 128))[lane] = s0;
    ((float4*)(g_spart + (((size_t)bh * SEGS + seg) * 64 + p + 1) * 128))[lane] = s1;
}

// ---------------- phase 2: carry initial states across segments ----------------
__global__ void carry_kernel()
{
    int bh = blockIdx.x;       // 32 blocks
    int tid = threadIdx.x;     // 256
    __shared__ float Ps[SEGS];
    if (tid < SEGS) Ps[tid] = g_e[(size_t)bh * Tseq + (size_t)(tid + 1) * QSEG - 1];
    __syncthreads();
    for (int k = 0; k < 32; k++) {
        int idx = tid + k * 256;  // p*128+n
        float sini = 0.f;
#pragma unroll
        for (int s = 1; s < SEGS; s++) {
            sini = g_spart[((size_t)bh * SEGS + (s - 1)) * 8192 + idx] + sini * Ps[s - 1];
            g_sinit[((size_t)bh * SEGS + s) * 8192 + idx] = sini;
        }
    }
}

// ---------------- phase 3: y[t,p] += e_t * (C_t . S_init) ----------------
__global__ __launch_bounds__(256)
void corr_kernel()
{
    int mt  = blockIdx.x;            // 0..5
    int seg = blockIdx.y + 1;        // 1..7
    int bh  = blockIdx.z;            // 0..31
    int b = bh >> 2, h = bh & 3;
    int t0 = seg * QSEG + mt * 128;
    if (g_e[(size_t)bh * Tseq + t0] == 0.f) return;

    __shared__ __align__(16) float Cs[BK][BM + 4];
    __shared__ __align__(16) float Ss[BK][68];
    const int tid = threadIdx.x;
    const int tx = tid & 15;
    const int ty = tid >> 4;
    const int lr = tid >> 2;
    const int lc = (tid & 3) << 2;

    const float* Abase = g_xbc + ((size_t)(b * Tseq + t0)) * 512 + 384;
    const float* Sbase = g_sinit + ((size_t)bh * SEGS + seg) * 8192;
    float acc[8][4];
#pragma unroll
    for (int i = 0; i < 8; i++)
#pragma unroll
        for (int j = 0; j < 4; j++) acc[i][j] = 0.f;

    const int mlim = QSEG - mt * 128;
    for (int k0 = 0; k0 < 128; k0 += BK) {
        float4 va = (lr < mlim) ? *(const float4*)(Abase + (size_t)lr * 512 + k0 + lc)
                                : make_float4(0.f, 0.f, 0.f, 0.f);
        float4 vb = (lr + 64 < mlim) ? *(const float4*)(Abase + (size_t)(lr + 64) * 512 + k0 + lc)
                                     : make_float4(0.f, 0.f, 0.f, 0.f);
        float4 vs = *(const float4*)(Sbase + (size_t)lr * 128 + k0 + lc);
        __syncthreads();
        Cs[lc + 0][lr] = va.x; Cs[lc + 1][lr] = va.y; Cs[lc + 2][lr] = va.z; Cs[lc + 3][lr] = va.w;
        Cs[lc + 0][lr + 64] = vb.x; Cs[lc + 1][lr + 64] = vb.y;
        Cs[lc + 2][lr + 64] = vb.z; Cs[lc + 3][lr + 64] = vb.w;
        Ss[lc + 0][lr] = vs.x; Ss[lc + 1][lr] = vs.y; Ss[lc + 2][lr] = vs.z; Ss[lc + 3][lr] = vs.w;
        __syncthreads();
#pragma unroll
        for (int kk = 0; kk < BK; kk++) {
            float4 a0 = *(const float4*)&Cs[kk][ty * 8];
            float4 a1 = *(const float4*)&Cs[kk][ty * 8 + 4];
            float4 bq = *(const float4*)&Ss[kk][tx * 4];
            float av[8] = {a0.x, a0.y, a0.z, a0.w, a1.x, a1.y, a1.z, a1.w};
            float bw[4] = {bq.x, bq.y, bq.z, bq.w};
#pragma unroll
            for (int i = 0; i < 8; i++)
#pragma unroll
                for (int j = 0; j < 4; j++)
                    acc[i][j] = fmaf(av[i], bw[j], acc[i][j]);
        }
    }
#pragma unroll
    for (int i = 0; i < 8; i++) {
        int mrow = ty * 8 + i;
        if (mrow >= mlim) continue;
        int tg = t0 + mrow;
        float e = g_e[(size_t)bh * Tseq + tg];
        float* yd = g_y + ((size_t)(b * Tseq + tg)) * EXPC + h * 64 + tx * 4;
        float4 old = *(float4*)yd;
        old.x += e * acc[i][0];
        old.y += e * acc[i][1];
        old.z += e * acc[i][2];
        old.w += e * acc[i][3];
        *(float4*)yd = old;
    }
}

// ---------------- (y + D*x) * silu(gate), rmsnorm(256); emits bf16 split ----------------
__global__ void gate_norm(const float* __restrict__ Dp, const float* __restrict__ gnw)
{
    int row = blockIdx.x;
    int tid = threadIdx.x;   // 256
    float xh = g_xbc[(size_t)row * 512 + tid];
    float yv = g_y[(size_t)row * EXPC + tid] + Dp[tid >> 6] * xh;
    float g  = g_proj[(size_t)row * PROJW + tid];
    float v  = yv * (g / (1.f + expf(-g)));
    float s = v * v;
#pragma unroll
    for (int o = 16; o > 0; o >>= 1) s += __shfl_xor_sync(0xffffffffu, s, o);
    __shared__ float ws[8];
    if ((tid & 31) == 0) ws[tid >> 5] = s;
    __syncthreads();
    float tot = 0.f;
#pragma unroll
    for (int i = 0; i < 8; i++) tot += ws[i];
    float sc = rsqrtf(tot * (1.f / EXPC) + 1e-5f);
    float outv = v * sc * gnw[tid];
    __nv_bfloat16 hi = __float2bfloat16(outv);
    g_ahi[(size_t)row * EXPC + tid] = hi;
    g_alo[(size_t)row * EXPC + tid] = __float2bfloat16(outv - __bfloat162float(hi));
}

// ---------------- combine the 4 directional outputs back to (B,L,DM) ----------------
__global__ void combine_kernel()
{
    int bl = blockIdx.x;
    int b = bl / Lseq, l = bl % Lseq;
    int hg = l / WGc, wg = l % WGc;
    int j = wg * HGc + hg;
    int tid = threadIdx.x;
    size_t base = (size_t)b * Tseq;
    float v = g_hn[(base + l) * DMc + tid]
            + g_hn[(base + Lseq + j) * DMc + tid]
            + g_hn[(base + 2 * Lseq + (Lseq - 1 - l)) * DMc + tid]
            + g_hn[(base + 3 * Lseq + (Lseq - 1 - j)) * DMc + tid];
    g_xm[(size_t)bl * DMc + tid] = v;
}

// ---------------- unpatchify to (B,CIN,340,720) ----------------
__global__ void unpatch(float* __restrict__ out)
{
    int idx = blockIdx.x * blockDim.x + threadIdx.x;
    if (idx >= NPATCH * PATCHK) return;
    int xc = idx % 720;
    int t1 = idx / 720;
    int y  = t1 % 340;
    int t2 = t1 / 340;
    int c  = t2 % 3;
    int b  = t2 / 3;
    int hg = y / PHc,  i  = y % PHc;
    int wg = xc / PWc, jj = xc % PWc;
    int l  = hg * WGc + wg;
    out[idx] = g_proj[((size_t)(b * Lseq + l)) * 480 + i * 24 + jj * 3 + c];
}

// ---------------- host orchestration ----------------
static float* sym_addr(const void* sym)
{
    void* p = nullptr;
    cudaGetSymbolAddress(&p, sym);
    return (float*)p;
}

extern "C" void kernel_launch(void* const* d_in, const int* in_sizes, int n_in,
                              void* d_out, int out_size)
{
    (void)in_sizes; (void)n_in; (void)out_size;
    const float* x       = (const float*)d_in[0];
    const float* W_pe    = (const float*)d_in[1];
    const float* b_pe    = (const float*)d_in[2];
    const float* norm_w  = (const float*)d_in[3];
    const float* in_w    = (const float*)d_in[4];
    const float* in_b    = (const float*)d_in[5];
    const float* conv_w  = (const float*)d_in[6];
    const float* conv_b  = (const float*)d_in[7];
    const float* dt_bias = (const float*)d_in[8];
    const float* A_log   = (const float*)d_in[9];
    const float* Dp      = (const float*)d_in[10];
    const float* gn_w    = (const float*)d_in[11];
    const float* out_w   = (const float*)d_in[12];
    const float* out_b   = (const float*)d_in[13];
    const float* normf_w = (const float*)d_in[14];
    const float* r1_w    = (const float*)d_in[15];
    const float* r1_b    = (const float*)d_in[16];
    const float* r2_w    = (const float*)d_in[17];
    const float* r2_b    = (const float*)d_in[18];
    float* out = (float*)d_out;

    float* patches = sym_addr(g_patches);
    float* emb     = sym_addr(g_emb);
    float* hbuf    = sym_addr(g_h);
    float* hn      = sym_addr(g_hn);
    float* proj    = sym_addr(g_proj);
    float* xm      = sym_addr(g_xm);
    __nv_bfloat16* ahi = (__nv_bfloat16*)sym_addr(g_ahi);
    __nv_bfloat16* alo = (__nv_bfloat16*)sym_addr(g_alo);
    __nv_bfloat16* whi = (__nv_bfloat16*)sym_addr(g_whi);
    __nv_bfloat16* wlo = (__nv_bfloat16*)sym_addr(g_wlo);

    static int smem_set = 0;
    if (!smem_set) {
        cudaFuncSetAttribute(mma_gemm, cudaFuncAttributeMaxDynamicSharedMemorySize, MMA_SMEM);
        smem_set = 1;
    }

    // patch embed with fused 4-direction scatter into g_h
    patch_gather<<<(NPATCH * PATCHK + 255) / 256, 256>>>(x);
    gemm128<<<dim3(1, (NPATCH + BM - 1) / BM), 256>>>(patches, W_pe, b_pe, nullptr,
                                                      hbuf, NPATCH, DMc, PATCHK, DMc, 2);

    const int MT = (BT + 127) / 128;   // 383 M-tiles
    for (int l = 0; l < 4; l++) {
        const float* iw = in_w + (size_t)l * 772 * DMc;
        const float* ib = in_b + (size_t)l * 772;
        wconv<<<(768 * 128 + 255) / 256, 256>>>(iw, 768 * 128);
        rmsnorm128<<<BT, 128>>>(hbuf, norm_w + l * DMc, hn, 1);
        mma_gemm<<<dim3(6, MT), 256, MMA_SMEM>>>(ahi, alo, whi, wlo, ib, nullptr,
                                                 proj, BT, DMc, PROJW, PROJW);
        dt_fused<<<BT / 8, 256>>>(hn, iw, ib, dt_bias + l * NHC, A_log + l * NHC);
        conv_silu<<<(int)(((size_t)BT * 512 + 255) / 256), 256>>>(
            conv_w + l * 512 * 4, conv_b + l * 512);
        e_kernel<<<32, 256>>>();
        scan_partial<<<2048, 128>>>();
        carry_kernel<<<32, 256>>>();
        corr_kernel<<<dim3(6, SEGS - 1, 32), 256>>>();
        gate_norm<<<BT, 256>>>(Dp + l * NHC, gn_w + l * EXPC);
        wconv<<<(128 * 256 + 255) / 256, 256>>>(out_w + (size_t)l * DMc * EXPC, 128 * 256);
        mma_gemm<<<dim3(1, MT), 256, MMA_SMEM>>>(ahi, alo, whi, wlo, out_b + l * DMc, hbuf,
                                                 hbuf, BT, EXPC, DMc, DMc);
    }

    rmsnorm128<<<BT, 128>>>(hbuf, normf_w, hn, 0);
    combine_kernel<<<NPATCH, 128>>>();
    gemm128<<<dim3(1, (NPATCH + BM - 1) / BM), 256>>>(xm, r1_w, r1_b, nullptr,
                                                      emb, NPATCH, DMc, DMc, DMc, 1);
    gemm128<<<dim3((480 + BN - 1) / BN, (NPATCH + BM - 1) / BM), 256>>>(
        emb, r2_w, r2_b, nullptr, proj, NPATCH, 480, DMc, 480, 0);
    unpatch<<<(NPATCH * PATCHK + 255) / 256, 256>>>(out);
}